// round 3
// baseline (speedup 1.0000x reference)
#include <cuda_runtime.h>
#include <math.h>

#define BATCH 64
#define WPOS  2048
#define NPOS  (BATCH * WPOS)      // 131072 positions
#define CH    64                  // channels per layer
#define MT    128                 // positions per block (kernel A)
#define NBLK_A (NPOS / MT)        // 1024
#define KC    128                 // K chunk for dense split-K
#define FLATK (WPOS * CH)         // 131072
#define GSPLIT (FLATK / KC)       // 1024

// Scratch (device globals — no allocation allowed)
__device__ __align__(16) float g_h4[(size_t)NPOS * CH];          // 32 MB
__device__ __align__(16) float g_part[(size_t)GSPLIT * 64 * 64]; // 16 MB

typedef unsigned long long u64;

__device__ __forceinline__ u64 pk2(float lo, float hi) {
    u64 r; asm("mov.b64 %0,{%1,%2};" : "=l"(r) : "f"(lo), "f"(hi)); return r;
}
__device__ __forceinline__ void upk2(u64 v, float& lo, float& hi) {
    asm("mov.b64 {%0,%1},%2;" : "=f"(lo), "=f"(hi) : "l"(v));
}
__device__ __forceinline__ u64 ffma2(u64 a, u64 b, u64 c) {
    u64 d; asm("fma.rn.f32x2 %0,%1,%2,%3;" : "=l"(d) : "l"(a), "l"(b), "l"(c)); return d;
}

__device__ __forceinline__ float hsig(float v) {
    return __saturatef(fmaf(v, 0.2f, 0.5f));
}
__device__ __forceinline__ float tanh_fast(float v) {
    float xc = fminf(fmaxf(v, -15.f), 15.f);
    float e = __expf(xc + xc);
    return __fdividef(e - 1.f, e + 1.f);
}

// ---------------------------------------------------------------------------
// Kernel A: fused 4x ConvLSTM layers. Each layer = per-position 64->192 matmul
// (f gate dead: c0==0; Wh dead: h0==0) + gate activations.
// Activations live in smem as DUPLICATED f32x2 pairs (a,a) so the FFMA2
// A-operand is a bare LDS.64 (no pack movs). Weights via LDS.128 -> two b64.
// Half-warps use staggered k (kk = k ^ stagger) to kill broadcast bank aliasing.
// ---------------------------------------------------------------------------
__global__ void __launch_bounds__(256, 2) k_lstm4(
    const float* __restrict__ x,
    const float* __restrict__ W0, const float* __restrict__ B0,
    const float* __restrict__ W1, const float* __restrict__ B1,
    const float* __restrict__ W2, const float* __restrict__ B2,
    const float* __restrict__ W3, const float* __restrict__ B3)
{
    extern __shared__ char smraw[];
    u64*   sh = (u64*)smraw;                       // act pairs [128][64] u64 (64 KB)
    float* Ws = (float*)(smraw + MT * CH * 8);     // weights [64][192] f32 (48 KB)
    float* Bs = Ws + CH * 192;                     // bias [192]

    const int tid = threadIdx.x;
    const int tx = tid & 15, ty = tid >> 4;
    const int m0 = ty * 8, c0 = tx * 4;
    const int kofs = (ty & 1) << 3;                // half-warp k stagger (8)
    const size_t p0 = (size_t)blockIdx.x * MT;

    {   // stage input as duplicated pairs: x float2 -> ulonglong2 STS.128
        const float2* xin = (const float2*)(x + p0 * CH);
        #pragma unroll
        for (int j = 0; j < 16; ++j) {
            int idx = tid + j * 256;               // float2 index, 4096 total
            float2 v = xin[idx];
            ulonglong2 w; w.x = pk2(v.x, v.x); w.y = pk2(v.y, v.y);
            *(ulonglong2*)&sh[idx * 2] = w;
        }
    }

    const float* Wl[4] = {W0, W1, W2, W3};
    const float* Bl[4] = {B0, B1, B2, B3};

    #pragma unroll 1
    for (int l = 0; l < 4; ++l) {
        const float* W  = Wl[l];
        const float* Bb = Bl[l];
        for (int i = tid; i < CH * 64; i += 256) {   // float4-indexed [64][256] slice
            int k  = i >> 6;
            int nq = (i & 63) << 2;
            float4 v = ((const float4*)W)[i];
            if (nq < 64)        *(float4*)&Ws[k * 192 + nq]      = v;  // i gate
            else if (nq >= 128) *(float4*)&Ws[k * 192 + nq - 64] = v;  // g, o gates
        }
        if (tid < 192) {
            int gate = tid >> 6, c = tid & 63;
            int gn = (gate == 0) ? c : (gate == 1 ? 128 + c : 192 + c);
            Bs[tid] = Bb[gn];
        }
        __syncthreads();

        u64 acc[3][2][8];
        #pragma unroll
        for (int g = 0; g < 3; ++g)
            #pragma unroll
            for (int jp = 0; jp < 2; ++jp)
                #pragma unroll
                for (int i = 0; i < 8; ++i) acc[g][jp][i] = 0ull;

        #pragma unroll 2
        for (int k = 0; k < CH; ++k) {
            const int kk = (k + kofs) & 63;
            u64 pa[8];
            #pragma unroll
            for (int i = 0; i < 8; ++i)
                pa[i] = sh[(m0 + i) * CH + kk];    // LDS.64, pre-duplicated
            const float* wr = Ws + kk * 192 + c0;
            #pragma unroll
            for (int g = 0; g < 3; ++g) {
                ulonglong2 bw = *(const ulonglong2*)(wr + g * 64);
                #pragma unroll
                for (int i = 0; i < 8; ++i) {
                    acc[g][0][i] = ffma2(pa[i], bw.x, acc[g][0][i]);
                    acc[g][1][i] = ffma2(pa[i], bw.y, acc[g][1][i]);
                }
            }
        }
        __syncthreads();   // reads of sh/Ws done -> safe to overwrite sh

        #pragma unroll
        for (int jp = 0; jp < 2; ++jp) {
            float bi0 = Bs[c0 + 2 * jp],       bi1 = Bs[c0 + 2 * jp + 1];
            float bg0 = Bs[64 + c0 + 2 * jp],  bg1 = Bs[64 + c0 + 2 * jp + 1];
            float bo0 = Bs[128 + c0 + 2 * jp], bo1 = Bs[128 + c0 + 2 * jp + 1];
            #pragma unroll
            for (int i = 0; i < 8; ++i) {
                float iv0, iv1, gv0, gv1, ov0, ov1;
                upk2(acc[0][jp][i], iv0, iv1);
                upk2(acc[1][jp][i], gv0, gv1);
                upk2(acc[2][jp][i], ov0, ov1);
                float cc0 = hsig(iv0 + bi0) * tanh_fast(gv0 + bg0);
                float cc1 = hsig(iv1 + bi1) * tanh_fast(gv1 + bg1);
                float hh0 = hsig(ov0 + bo0) * tanh_fast(cc0);
                float hh1 = hsig(ov1 + bo1) * tanh_fast(cc1);
                sh[(m0 + i) * CH + c0 + 2 * jp]     = pk2(hh0, hh0);
                sh[(m0 + i) * CH + c0 + 2 * jp + 1] = pk2(hh1, hh1);
            }
        }
        __syncthreads();
    }

    {   // store layer-4 h (== flat) to gmem, float4 coalesced
        float4* hout = (float4*)(g_h4 + p0 * CH);
        #pragma unroll
        for (int j = 0; j < 8; ++j) {
            int idx = tid + j * 256;               // float4 index, 2048 total
            const u64* s = &sh[idx * 4];
            float a0, a1, a2, a3, d;
            upk2(s[0], a0, d); upk2(s[1], a1, d);
            upk2(s[2], a2, d); upk2(s[3], a3, d);
            hout[idx] = make_float4(a0, a1, a2, a3);
        }
    }
}

// ---------------------------------------------------------------------------
// Kernel B: split-K GEMM  partial[g] = flat[:, kb:kb+128] @ D1w[kb:kb+128, :]
// ---------------------------------------------------------------------------
__global__ void __launch_bounds__(256) k_dense_split(const float* __restrict__ D1w)
{
    extern __shared__ float sm[];
    float* As  = sm;             // [64][128]
    float* Bsm = sm + 64 * KC;   // [128][64]
    const int tid = threadIdx.x;
    const size_t kbase = (size_t)blockIdx.x * KC;

    for (int i = tid; i < 64 * (KC / 4); i += 256) {
        int b = i / (KC / 4), kq = i % (KC / 4);
        ((float4*)As)[i] = *(const float4*)(g_h4 + (size_t)b * FLATK + kbase + (size_t)kq * 4);
    }
    {
        const float4* d1 = (const float4*)(D1w + kbase * 64);
        for (int i = tid; i < KC * 16; i += 256) ((float4*)Bsm)[i] = d1[i];
    }
    __syncthreads();

    const int tx = tid & 15, ty = tid >> 4;
    const int b0 = ty * 4, n0 = tx * 4;
    u64 acc[4][2] = {};
    #pragma unroll 4
    for (int k = 0; k < KC; ++k) {
        ulonglong2 bw = *(const ulonglong2*)&Bsm[k * 64 + n0];
        #pragma unroll
        for (int j = 0; j < 4; ++j) {
            float a = As[(b0 + j) * KC + k];
            u64 pa = pk2(a, a);
            acc[j][0] = ffma2(pa, bw.x, acc[j][0]);
            acc[j][1] = ffma2(pa, bw.y, acc[j][1]);
        }
    }
    float* dst = g_part + (size_t)blockIdx.x * 4096;
    #pragma unroll
    for (int j = 0; j < 4; ++j) {
        float a0, a1, a2, a3;
        upk2(acc[j][0], a0, a1);
        upk2(acc[j][1], a2, a3);
        *(float4*)&dst[(b0 + j) * 64 + n0] = make_float4(a0, a1, a2, a3);
    }
}

// ---------------------------------------------------------------------------
// Kernel C: fixed-order reduce of 1024 partials + D1b + relu + D2 GEMV.
// ---------------------------------------------------------------------------
__global__ void k_final(const float* __restrict__ D1b, const float* __restrict__ D2w,
                        const float* __restrict__ D2b, float* __restrict__ out)
{
    __shared__ float sred[256];
    __shared__ float sA[2];
    const int b = blockIdx.x, tid = threadIdx.x;
    const int n = tid & 63, slice = tid >> 6;
    const float* p = g_part + (size_t)slice * (GSPLIT / 4) * 4096 + (size_t)b * 64 + n;
    float s = 0.f;
    #pragma unroll 8
    for (int g = 0; g < GSPLIT / 4; ++g) s += p[(size_t)g * 4096];
    sred[tid] = s;
    __syncthreads();
    if (tid < 64) {
        float v = sred[tid] + sred[tid + 64] + sred[tid + 128] + sred[tid + 192];
        float y = fmaxf(v + D1b[n], 0.f) * D2w[n];
        #pragma unroll
        for (int off = 16; off > 0; off >>= 1)
            y += __shfl_down_sync(0xffffffffu, y, off);
        if ((tid & 31) == 0) sA[tid >> 5] = y;
    }
    __syncthreads();
    if (tid == 0) out[b] = sA[0] + sA[1] + D2b[0];
}

// ---------------------------------------------------------------------------
extern "C" void kernel_launch(void* const* d_in, const int* in_sizes, int n_in,
                              void* d_out, int out_size)
{
    const float* x   = (const float*)d_in[0];
    const float* W1x = (const float*)d_in[1];
    const float* b1  = (const float*)d_in[3];
    const float* W2x = (const float*)d_in[4];
    const float* b2  = (const float*)d_in[6];
    const float* W3x = (const float*)d_in[7];
    const float* b3  = (const float*)d_in[9];
    const float* W4x = (const float*)d_in[10];
    const float* b4  = (const float*)d_in[12];
    const float* D1w = (const float*)d_in[13];
    const float* D1b = (const float*)d_in[14];
    const float* D2w = (const float*)d_in[15];
    const float* D2b = (const float*)d_in[16];

    const int smemA = MT * CH * 8 + CH * 192 * 4 + 192 * 4;   // 115456 B
    const int smemB = (64 * KC + KC * 64) * 4;                // 65536 B
    cudaFuncSetAttribute(k_lstm4, cudaFuncAttributeMaxDynamicSharedMemorySize, smemA);
    cudaFuncSetAttribute(k_dense_split, cudaFuncAttributeMaxDynamicSharedMemorySize, smemB);

    // SAME padding over H=1 picks exactly one kernel row: r=4 (kh=10), r=2 (kh=5)
    k_lstm4<<<NBLK_A, 256, smemA>>>(x,
        W1x + 4 * 64 * 256, b1,
        W2x + 2 * 64 * 256, b2,
        W3x + 4 * 64 * 256, b3,
        W4x + 2 * 64 * 256, b4);
    k_dense_split<<<GSPLIT, 256, smemB>>>(D1w);
    k_final<<<BATCH, 256>>>(D1b, D2w, D2b, (float*)d_out);
}

// round 5
// speedup vs baseline: 1.4366x; 1.4366x over previous
#include <cuda_runtime.h>
#include <cuda_bf16.h>
#include <cstdint>
#include <math.h>

#define BATCH 64
#define WPOS  2048
#define NPOS  (BATCH * WPOS)      // 131072 positions
#define CH    64
#define MTILE 64                  // positions per block (kernel A)
#define NBLK_A (NPOS / MTILE)     // 2048
#define KC    128                 // K chunk for dense split-K
#define FLATK (WPOS * CH)         // 131072
#define GSPLIT (FLATK / KC)       // 1024
#define NW    192                 // gates i,g,o (f gate dead)

// ---- scratch (device globals; no allocation allowed) -----------------------
__device__ __align__(16) float g_h4[(size_t)NPOS * CH];            // 32 MB
__device__ __align__(16) float g_part[(size_t)GSPLIT * 64 * 64];   // 16 MB
__device__ __align__(16) unsigned short g_Wsp[4][2][NW * 64];      // pre-swizzled bf16 hi/lo
__device__ __align__(16) float g_Bp[4][NW];

typedef unsigned long long u64;

__device__ __forceinline__ u64 pk2(float lo, float hi) {
    u64 r; asm("mov.b64 %0,{%1,%2};" : "=l"(r) : "f"(lo), "f"(hi)); return r;
}
__device__ __forceinline__ void upk2(u64 v, float& lo, float& hi) {
    asm("mov.b64 {%0,%1},%2;" : "=f"(lo), "=f"(hi) : "l"(v));
}
__device__ __forceinline__ u64 ffma2(u64 a, u64 b, u64 c) {
    u64 d; asm("fma.rn.f32x2 %0,%1,%2,%3;" : "=l"(d) : "l"(a), "l"(b), "l"(c)); return d;
}
__device__ __forceinline__ float hsig(float v) {
    return __saturatef(fmaf(v, 0.2f, 0.5f));
}
__device__ __forceinline__ float tanh_fast(float v) {
    float xc = fminf(fmaxf(v, -15.f), 15.f);
    float e = __expf(xc + xc);
    return __fdividef(e - 1.f, e + 1.f);
}
__device__ __forceinline__ uint32_t smem_u32(const void* p) {
    uint32_t a;
    asm("{ .reg .u64 t; cvta.to.shared.u64 t, %1; cvt.u32.u64 %0, t; }" : "=r"(a) : "l"(p));
    return a;
}

// warp-level mma + ldmatrix (plain sm_80+ PTX; no 'a'-gated features)
__device__ __forceinline__ void mma16816(float* c, const uint32_t* a, uint32_t b0, uint32_t b1) {
    asm volatile(
        "mma.sync.aligned.m16n8k16.row.col.f32.bf16.bf16.f32 "
        "{%0,%1,%2,%3},{%4,%5,%6,%7},{%8,%9},{%0,%1,%2,%3};"
        : "+f"(c[0]), "+f"(c[1]), "+f"(c[2]), "+f"(c[3])
        : "r"(a[0]), "r"(a[1]), "r"(a[2]), "r"(a[3]), "r"(b0), "r"(b1));
}
#define LDSM_X4(r, a) \
    asm volatile("ldmatrix.sync.aligned.m8n8.x4.shared.b16 {%0,%1,%2,%3}, [%4];" \
        : "=r"((r)[0]), "=r"((r)[1]), "=r"((r)[2]), "=r"((r)[3]) : "r"(a))

__device__ __forceinline__ u64 pack4bf(float a, float b, float c, float d) {
    return (u64)__bfloat16_as_ushort(__float2bfloat16(a))
         | ((u64)__bfloat16_as_ushort(__float2bfloat16(b)) << 16)
         | ((u64)__bfloat16_as_ushort(__float2bfloat16(c)) << 32)
         | ((u64)__bfloat16_as_ushort(__float2bfloat16(d)) << 48);
}

// smem layout (bytes)
#define A_HI   0        // [64 rows][64 bf16], XOR-swizzled rows, 8192 B
#define A_LO   8192
#define B_HI   16384    // [192 n][64 k] bf16 hi, 24576 B (z buffer reuses B area)
#define B_LO   40960
#define BIAS   65536    // 4*192 f32
#define SMEM_A_TOT 68608
#define ZOFF   B_HI     // z[64][192] f32 = 49152 B, exactly the B region

// ---------------------------------------------------------------------------
// Prep: bf16 hi/lo split of the 4 weight slices, transposed to [n][k],
// XOR row swizzle pre-applied so blocks copy verbatim. Gate-packed biases.
// ---------------------------------------------------------------------------
__global__ void k_prep(const float* __restrict__ W0, const float* __restrict__ W1,
                       const float* __restrict__ W2, const float* __restrict__ W3,
                       const float* __restrict__ B0, const float* __restrict__ B1,
                       const float* __restrict__ B2, const float* __restrict__ B3)
{
    const int l = blockIdx.x, tid = threadIdx.x;
    const float* W  = (l == 0) ? W0 : (l == 1) ? W1 : (l == 2) ? W2 : W3;
    const float* Bb = (l == 0) ? B0 : (l == 1) ? B1 : (l == 2) ? B2 : B3;
    for (int idx = tid; idx < NW * 64; idx += 256) {
        int n = idx >> 6, k = idx & 63;
        int gn = (n < 64) ? n : n + 64;        // skip dead f gate
        float w = W[k * 256 + gn];
        __nv_bfloat16 hb = __float2bfloat16(w);
        __nv_bfloat16 lb = __float2bfloat16(w - __bfloat162float(hb));
        uint32_t sw = (uint32_t)n * 64 + ((((uint32_t)(2 * k)) ^ (((uint32_t)n & 7) << 4)) >> 1);
        g_Wsp[l][0][sw] = __bfloat16_as_ushort(hb);
        g_Wsp[l][1][sw] = __bfloat16_as_ushort(lb);
    }
    for (int n = tid; n < NW; n += 256) {
        int gn = (n < 64) ? n : n + 64;
        g_Bp[l][n] = Bb[gn];
    }
}

// ---------------------------------------------------------------------------
// Kernel A: fused 4x ConvLSTM via mma.sync bf16x3 (hi*hi + hi*lo + lo*hi).
// 64-position tile, 8 warps, each warp [16m x 96n]. z staged in B smem region
// for the cross-warp gate gather; h re-split to bf16 hi/lo in place.
// ---------------------------------------------------------------------------
__global__ void __launch_bounds__(256, 2) k_lstm4(const float* __restrict__ x)
{
    extern __shared__ char sm[];
    const uint32_t sb = smem_u32(sm);
    const int tid = threadIdx.x;
    const int wid = tid >> 5, lane = tid & 31;
    const int g8 = lane >> 2, tig = lane & 3;
    const size_t p0 = (size_t)blockIdx.x * MTILE;

    // biases -> smem
    float* bs = (float*)(sm + BIAS);
    #pragma unroll
    for (int i = 0; i < 3; ++i) bs[tid + i * 256] = ((const float*)g_Bp)[tid + i * 256];

    // stage input tile as bf16 hi/lo, XOR row swizzle
    {
        const float4* xin = (const float4*)(x + p0 * CH);
        #pragma unroll
        for (int i = 0; i < 4; ++i) {
            int fi = tid + i * 256;                 // 1024 float4
            int pos = fi >> 4, c = (fi & 15) << 2;
            float4 v = xin[fi];
            float h0 = __bfloat162float(__float2bfloat16(v.x));
            float h1 = __bfloat162float(__float2bfloat16(v.y));
            float h2 = __bfloat162float(__float2bfloat16(v.z));
            float h3 = __bfloat162float(__float2bfloat16(v.w));
            uint32_t b = (uint32_t)pos * 128 + (((uint32_t)(2 * c)) ^ (((uint32_t)pos & 7) << 4));
            *(u64*)(sm + A_HI + b) = pack4bf(v.x, v.y, v.z, v.w);
            *(u64*)(sm + A_LO + b) = pack4bf(v.x - h0, v.y - h1, v.z - h2, v.w - h3);
        }
    }

    // ldmatrix lane roles
    const int lt = lane >> 3, lr = lane & 7;
    const int mrow = (wid & 3) * 16, n0 = (wid >> 2) * 96;
    const int arow = mrow + ((lt & 1) << 3) + lr;
    const uint32_t a_rowbase = sb + (uint32_t)arow * 128;
    const uint32_t aswz = ((uint32_t)arow & 7) << 4;
    const int akadd = (lt >> 1) << 4;
    const int brow0 = n0 + ((lt >> 1) << 3) + lr;
    const uint32_t bswz = ((uint32_t)brow0 & 7) << 4;
    const int bkadd = (lt & 1) << 4;

    #pragma unroll 1
    for (int l = 0; l < 4; ++l) {
        __syncthreads();   // A tile ready (stage/epilogue) & z reads done
        {   // copy pre-swizzled weights: 49152 B (hi then lo, contiguous)
            const uint4* src = (const uint4*)g_Wsp[l];
            uint4* dst = (uint4*)(sm + B_HI);
            #pragma unroll
            for (int i = 0; i < 12; ++i) dst[tid + i * 256] = src[tid + i * 256];
        }
        __syncthreads();

        float acc[12][4];
        #pragma unroll
        for (int nt = 0; nt < 12; ++nt)
            #pragma unroll
            for (int r = 0; r < 4; ++r) acc[nt][r] = 0.f;

        #pragma unroll 1
        for (int s = 0; s < 3; ++s) {
            const uint32_t Abase = (s == 2) ? A_LO : A_HI;
            const uint32_t Bbase = sb + ((s == 1) ? B_LO : B_HI);
            #pragma unroll
            for (int ks = 0; ks < 4; ++ks) {
                const uint32_t kb = ks * 32;
                uint32_t a[4];
                LDSM_X4(a, a_rowbase + Abase + ((kb + akadd) ^ aswz));
                #pragma unroll
                for (int np = 0; np < 6; ++np) {
                    uint32_t b[4];
                    uint32_t baddr = Bbase + (uint32_t)(brow0 + np * 16) * 128
                                   + ((kb + bkadd) ^ bswz);
                    LDSM_X4(b, baddr);
                    mma16816(acc[2 * np],     a, b[0], b[1]);
                    mma16816(acc[2 * np + 1], a, b[2], b[3]);
                }
            }
        }
        __syncthreads();   // all MMA smem reads done -> B region becomes z

        // scatter z = acc into [64][192] f32 (swizzled 8B units)
        #pragma unroll
        for (int nt = 0; nt < 12; ++nt) {
            int n = n0 + nt * 8 + tig * 2;
            int m = mrow + g8;
            uint32_t b0 = (uint32_t)m * 768 + (((uint32_t)(n * 4)) ^ (((uint32_t)m & 7) << 4));
            *(float2*)(sm + ZOFF + b0) = make_float2(acc[nt][0], acc[nt][1]);
            int m2 = m + 8;
            uint32_t b1 = (uint32_t)m2 * 768 + (((uint32_t)(n * 4)) ^ (((uint32_t)m2 & 7) << 4));
            *(float2*)(sm + ZOFF + b1) = make_float2(acc[nt][2], acc[nt][3]);
        }
        __syncthreads();

        // gate phase: thread -> (m = tid>>2, 16 channels)
        const int gm = tid >> 2, cb = (tid & 3) * 16;
        const uint32_t msw = ((uint32_t)gm & 7) << 4;
        const uint32_t zrow = (uint32_t)gm * 768;
        const float* bl = bs + l * NW;
        #pragma unroll
        for (int q = 0; q < 4; ++q) {
            int c = cb + q * 4;
            float2 i01 = *(float2*)(sm + ZOFF + zrow + (((uint32_t)(c * 4)) ^ msw));
            float2 i23 = *(float2*)(sm + ZOFF + zrow + (((uint32_t)((c + 2) * 4)) ^ msw));
            float2 g01 = *(float2*)(sm + ZOFF + zrow + (((uint32_t)((64 + c) * 4)) ^ msw));
            float2 g23 = *(float2*)(sm + ZOFF + zrow + (((uint32_t)((66 + c) * 4)) ^ msw));
            float2 o01 = *(float2*)(sm + ZOFF + zrow + (((uint32_t)((128 + c) * 4)) ^ msw));
            float2 o23 = *(float2*)(sm + ZOFF + zrow + (((uint32_t)((130 + c) * 4)) ^ msw));
            float h[4];
            h[0] = hsig(o01.x + bl[128 + c])     * tanh_fast(hsig(i01.x + bl[c])     * tanh_fast(g01.x + bl[64 + c]));
            h[1] = hsig(o01.y + bl[128 + c + 1]) * tanh_fast(hsig(i01.y + bl[c + 1]) * tanh_fast(g01.y + bl[64 + c + 1]));
            h[2] = hsig(o23.x + bl[128 + c + 2]) * tanh_fast(hsig(i23.x + bl[c + 2]) * tanh_fast(g23.x + bl[64 + c + 2]));
            h[3] = hsig(o23.y + bl[128 + c + 3]) * tanh_fast(hsig(i23.y + bl[c + 3]) * tanh_fast(g23.y + bl[64 + c + 3]));
            if (l < 3) {
                float d0 = __bfloat162float(__float2bfloat16(h[0]));
                float d1 = __bfloat162float(__float2bfloat16(h[1]));
                float d2 = __bfloat162float(__float2bfloat16(h[2]));
                float d3 = __bfloat162float(__float2bfloat16(h[3]));
                uint32_t b = (uint32_t)gm * 128 + (((uint32_t)(2 * c)) ^ msw);
                *(u64*)(sm + A_HI + b) = pack4bf(h[0], h[1], h[2], h[3]);
                *(u64*)(sm + A_LO + b) = pack4bf(h[0] - d0, h[1] - d1, h[2] - d2, h[3] - d3);
            } else {
                *(float4*)&g_h4[(p0 + gm) * CH + c] = make_float4(h[0], h[1], h[2], h[3]);
            }
        }
    }
}

// ---------------------------------------------------------------------------
// Kernel B: split-K GEMM  partial[g] = flat[:, kb:kb+128] @ D1w[kb:kb+128, :]
// ---------------------------------------------------------------------------
__global__ void __launch_bounds__(256) k_dense_split(const float* __restrict__ D1w)
{
    extern __shared__ float smf[];
    float* As  = smf;             // [64][128]
    float* Bsm = smf + 64 * KC;   // [128][64]
    const int tid = threadIdx.x;
    const size_t kbase = (size_t)blockIdx.x * KC;

    for (int i = tid; i < 64 * (KC / 4); i += 256) {
        int b = i / (KC / 4), kq = i % (KC / 4);
        ((float4*)As)[i] = *(const float4*)(g_h4 + (size_t)b * FLATK + kbase + (size_t)kq * 4);
    }
    {
        const float4* d1 = (const float4*)(D1w + kbase * 64);
        for (int i = tid; i < KC * 16; i += 256) ((float4*)Bsm)[i] = d1[i];
    }
    __syncthreads();

    const int tx = tid & 15, ty = tid >> 4;
    const int b0 = ty * 4, n0 = tx * 4;
    u64 acc[4][2] = {};
    #pragma unroll 4
    for (int k = 0; k < KC; ++k) {
        ulonglong2 bw = *(const ulonglong2*)&Bsm[k * 64 + n0];
        #pragma unroll
        for (int j = 0; j < 4; ++j) {
            float a = As[(b0 + j) * KC + k];
            u64 pa = pk2(a, a);
            acc[j][0] = ffma2(pa, bw.x, acc[j][0]);
            acc[j][1] = ffma2(pa, bw.y, acc[j][1]);
        }
    }
    float* dst = g_part + (size_t)blockIdx.x * 4096;
    #pragma unroll
    for (int j = 0; j < 4; ++j) {
        float a0, a1, a2, a3;
        upk2(acc[j][0], a0, a1);
        upk2(acc[j][1], a2, a3);
        *(float4*)&dst[(b0 + j) * 64 + n0] = make_float4(a0, a1, a2, a3);
    }
}

// ---------------------------------------------------------------------------
// Kernel C: fixed-order reduce of 1024 partials + D1b + relu + D2 GEMV.
// ---------------------------------------------------------------------------
__global__ void k_final(const float* __restrict__ D1b, const float* __restrict__ D2w,
                        const float* __restrict__ D2b, float* __restrict__ out)
{
    __shared__ float sred[256];
    __shared__ float sA[2];
    const int b = blockIdx.x, tid = threadIdx.x;
    const int n = tid & 63, slice = tid >> 6;
    const float* p = g_part + (size_t)slice * (GSPLIT / 4) * 4096 + (size_t)b * 64 + n;
    float s = 0.f;
    #pragma unroll 8
    for (int g = 0; g < GSPLIT / 4; ++g) s += p[(size_t)g * 4096];
    sred[tid] = s;
    __syncthreads();
    if (tid < 64) {
        float v = sred[tid] + sred[tid + 64] + sred[tid + 128] + sred[tid + 192];
        float y = fmaxf(v + D1b[n], 0.f) * D2w[n];
        #pragma unroll
        for (int off = 16; off > 0; off >>= 1)
            y += __shfl_down_sync(0xffffffffu, y, off);
        if ((tid & 31) == 0) sA[tid >> 5] = y;
    }
    __syncthreads();
    if (tid == 0) out[b] = sA[0] + sA[1] + D2b[0];
}

// ---------------------------------------------------------------------------
extern "C" void kernel_launch(void* const* d_in, const int* in_sizes, int n_in,
                              void* d_out, int out_size)
{
    const float* x   = (const float*)d_in[0];
    const float* W1x = (const float*)d_in[1];
    const float* b1  = (const float*)d_in[3];
    const float* W2x = (const float*)d_in[4];
    const float* b2  = (const float*)d_in[6];
    const float* W3x = (const float*)d_in[7];
    const float* b3  = (const float*)d_in[9];
    const float* W4x = (const float*)d_in[10];
    const float* b4  = (const float*)d_in[12];
    const float* D1w = (const float*)d_in[13];
    const float* D1b = (const float*)d_in[14];
    const float* D2w = (const float*)d_in[15];
    const float* D2b = (const float*)d_in[16];

    const int smemB = (64 * KC + KC * 64) * 4;   // 65536 B
    cudaFuncSetAttribute(k_lstm4, cudaFuncAttributeMaxDynamicSharedMemorySize, SMEM_A_TOT);
    cudaFuncSetAttribute(k_dense_split, cudaFuncAttributeMaxDynamicSharedMemorySize, smemB);

    // SAME padding over H=1 picks exactly one kernel row: r=4 (kh=10), r=2 (kh=5)
    k_prep<<<4, 256>>>(W1x + 4 * 64 * 256, W2x + 2 * 64 * 256,
                       W3x + 4 * 64 * 256, W4x + 2 * 64 * 256,
                       b1, b2, b3, b4);
    k_lstm4<<<NBLK_A, 256, SMEM_A_TOT>>>(x);
    k_dense_split<<<GSPLIT, 256, smemB>>>(D1w);
    k_final<<<BATCH, 256>>>(D1b, D2w, D2b, (float*)d_out);
}

// round 6
// speedup vs baseline: 1.8085x; 1.2588x over previous
#include <cuda_runtime.h>
#include <cuda_bf16.h>
#include <cstdint>
#include <math.h>

#define BATCH 64
#define WPOS  2048
#define NPOS  (BATCH * WPOS)      // 131072 positions
#define CH    64
#define MTILE 64                  // positions per block (kernel A)
#define NBLK_A (NPOS / MTILE)     // 2048
#define KC    128                 // K chunk for dense split-K
#define FLATK (WPOS * CH)         // 131072
#define GSPLIT (FLATK / KC)       // 1024
#define NW    192                 // gates i,g,o (f gate dead)

// ---- scratch (device globals; no allocation allowed) -----------------------
__device__ __align__(16) float g_h4[(size_t)NPOS * CH];            // 32 MB
__device__ __align__(16) float g_part[(size_t)GSPLIT * 64 * 64];   // 16 MB
__device__ __align__(16) float g_red[8 * 64 * 64];                 // 128 KB
__device__ __align__(16) unsigned short g_Wsp[4][2][NW * 64];      // pre-swizzled bf16 hi/lo
__device__ __align__(16) float g_Bp[4][NW];

typedef unsigned long long u64;

__device__ __forceinline__ u64 pk2(float lo, float hi) {
    u64 r; asm("mov.b64 %0,{%1,%2};" : "=l"(r) : "f"(lo), "f"(hi)); return r;
}
__device__ __forceinline__ void upk2(u64 v, float& lo, float& hi) {
    asm("mov.b64 {%0,%1},%2;" : "=f"(lo), "=f"(hi) : "l"(v));
}
__device__ __forceinline__ u64 ffma2(u64 a, u64 b, u64 c) {
    u64 d; asm("fma.rn.f32x2 %0,%1,%2,%3;" : "=l"(d) : "l"(a), "l"(b), "l"(c)); return d;
}
__device__ __forceinline__ float hsig(float v) {
    return __saturatef(fmaf(v, 0.2f, 0.5f));
}
__device__ __forceinline__ float tanh_fast(float v) {
    float xc = fminf(fmaxf(v, -15.f), 15.f);
    float e = __expf(xc + xc);
    return __fdividef(e - 1.f, e + 1.f);
}
__device__ __forceinline__ uint32_t smem_u32(const void* p) {
    uint32_t a;
    asm("{ .reg .u64 t; cvta.to.shared.u64 t, %1; cvt.u32.u64 %0, t; }" : "=r"(a) : "l"(p));
    return a;
}

// warp-level mma + ldmatrix (plain sm_80+ PTX; tcgen05 is 'a'-gated -> unusable here)
__device__ __forceinline__ void mma16816(float* c, const uint32_t* a, uint32_t b0, uint32_t b1) {
    asm volatile(
        "mma.sync.aligned.m16n8k16.row.col.f32.bf16.bf16.f32 "
        "{%0,%1,%2,%3},{%4,%5,%6,%7},{%8,%9},{%0,%1,%2,%3};"
        : "+f"(c[0]), "+f"(c[1]), "+f"(c[2]), "+f"(c[3])
        : "r"(a[0]), "r"(a[1]), "r"(a[2]), "r"(a[3]), "r"(b0), "r"(b1));
}
#define LDSM_X4(r, a) \
    asm volatile("ldmatrix.sync.aligned.m8n8.x4.shared.b16 {%0,%1,%2,%3}, [%4];" \
        : "=r"((r)[0]), "=r"((r)[1]), "=r"((r)[2]), "=r"((r)[3]) : "r"(a))

__device__ __forceinline__ u64 pack4bf(float a, float b, float c, float d) {
    return (u64)__bfloat16_as_ushort(__float2bfloat16(a))
         | ((u64)__bfloat16_as_ushort(__float2bfloat16(b)) << 16)
         | ((u64)__bfloat16_as_ushort(__float2bfloat16(c)) << 32)
         | ((u64)__bfloat16_as_ushort(__float2bfloat16(d)) << 48);
}
__device__ __forceinline__ uint32_t pk2bf(float a, float b) {
    return (uint32_t)__bfloat16_as_ushort(__float2bfloat16(a))
         | ((uint32_t)__bfloat16_as_ushort(__float2bfloat16(b)) << 16);
}

// smem layout (bytes)
#define A_HI   0        // [64 rows][64 bf16], XOR-swizzled rows, 8192 B
#define A_LO   8192
#define B_HI   16384    // [192 n][64 k] bf16 hi, 24576 B
#define B_LO   40960
#define BIAS   65536    // 4*192 f32
#define SMEM_A_TOT 68608

// ---------------------------------------------------------------------------
// Prep: bf16 hi/lo split of the 4 weight slices, GATE-INTERLEAVED n-order:
//   n = half*96 + j*24 + gate*8 + e  ->  channel c = half*32 + j*8 + e
// so each mma thread's fragment holds i/g/o of the SAME channels (register
// epilogue, no cross-warp z exchange). XOR row swizzle pre-applied.
// ---------------------------------------------------------------------------
__global__ void k_prep(const float* __restrict__ W0, const float* __restrict__ W1,
                       const float* __restrict__ W2, const float* __restrict__ W3,
                       const float* __restrict__ B0, const float* __restrict__ B1,
                       const float* __restrict__ B2, const float* __restrict__ B3)
{
    const int l = blockIdx.x, tid = threadIdx.x;
    const float* W  = (l == 0) ? W0 : (l == 1) ? W1 : (l == 2) ? W2 : W3;
    const float* Bb = (l == 0) ? B0 : (l == 1) ? B1 : (l == 2) ? B2 : B3;
    for (int idx = tid; idx < NW * 64; idx += 256) {
        int n = idx >> 6, k = idx & 63;
        int half = n / 96, r = n % 96;
        int j = r / 24, gate = (r % 24) >> 3, e = r & 7;
        int c = half * 32 + j * 8 + e;
        int gn = (gate == 0) ? c : (gate == 1) ? 128 + c : 192 + c;   // skip dead f gate
        float w = W[k * 256 + gn];
        __nv_bfloat16 hb = __float2bfloat16(w);
        __nv_bfloat16 lb = __float2bfloat16(w - __bfloat162float(hb));
        uint32_t sw = (uint32_t)n * 64 + ((((uint32_t)(2 * k)) ^ (((uint32_t)n & 7) << 4)) >> 1);
        g_Wsp[l][0][sw] = __bfloat16_as_ushort(hb);
        g_Wsp[l][1][sw] = __bfloat16_as_ushort(lb);
    }
    for (int n = tid; n < NW; n += 256) {
        int half = n / 96, r = n % 96;
        int j = r / 24, gate = (r % 24) >> 3, e = r & 7;
        int c = half * 32 + j * 8 + e;
        int gn = (gate == 0) ? c : (gate == 1) ? 128 + c : 192 + c;
        g_Bp[l][n] = Bb[gn];
    }
}

// ---------------------------------------------------------------------------
// Kernel A: fused 4x ConvLSTM via mma.sync bf16x3 (hi*hi + hi*lo + lo*hi).
// 64-position tile, 8 warps, each warp [16m x 96n]; gate-interleaved columns
// mean the whole gate epilogue stays in registers. 2 syncthreads per layer.
// ---------------------------------------------------------------------------
__global__ void __launch_bounds__(256, 2) k_lstm4(const float* __restrict__ x)
{
    extern __shared__ char sm[];
    const uint32_t sb = smem_u32(sm);
    const int tid = threadIdx.x;
    const int wid = tid >> 5, lane = tid & 31;
    const int g8 = lane >> 2, tig = lane & 3;
    const size_t p0 = (size_t)blockIdx.x * MTILE;

    // biases -> smem
    float* bs = (float*)(sm + BIAS);
    #pragma unroll
    for (int i = 0; i < 3; ++i) bs[tid + i * 256] = ((const float*)g_Bp)[tid + i * 256];

    // stage input tile as bf16 hi/lo, XOR row swizzle
    {
        const float4* xin = (const float4*)(x + p0 * CH);
        #pragma unroll
        for (int i = 0; i < 4; ++i) {
            int fi = tid + i * 256;                 // 1024 float4
            int pos = fi >> 4, c = (fi & 15) << 2;
            float4 v = xin[fi];
            float h0 = __bfloat162float(__float2bfloat16(v.x));
            float h1 = __bfloat162float(__float2bfloat16(v.y));
            float h2 = __bfloat162float(__float2bfloat16(v.z));
            float h3 = __bfloat162float(__float2bfloat16(v.w));
            uint32_t b = (uint32_t)pos * 128 + (((uint32_t)(2 * c)) ^ (((uint32_t)pos & 7) << 4));
            *(u64*)(sm + A_HI + b) = pack4bf(v.x, v.y, v.z, v.w);
            *(u64*)(sm + A_LO + b) = pack4bf(v.x - h0, v.y - h1, v.z - h2, v.w - h3);
        }
    }

    // ldmatrix lane roles
    const int lt = lane >> 3, lr = lane & 7;
    const int mrow = (wid & 3) * 16, n0 = (wid >> 2) * 96, chb = (wid >> 2) * 32;
    const int arow = mrow + ((lt & 1) << 3) + lr;
    const uint32_t a_rowbase = sb + (uint32_t)arow * 128;
    const uint32_t aswz = ((uint32_t)arow & 7) << 4;
    const int akadd = (lt >> 1) << 4;
    const int brow0 = n0 + ((lt >> 1) << 3) + lr;
    const uint32_t bswz = ((uint32_t)brow0 & 7) << 4;
    const int bkadd = (lt & 1) << 4;
    const int m1 = mrow + g8;           // fragment rows
    const int m2 = m1 + 8;

    #pragma unroll 1
    for (int l = 0; l < 4; ++l) {
        {   // copy pre-swizzled weights: 49152 B (hi then lo, contiguous)
            const uint4* src = (const uint4*)g_Wsp[l];
            uint4* dst = (uint4*)(sm + B_HI);
            #pragma unroll
            for (int i = 0; i < 12; ++i) dst[tid + i * 256] = src[tid + i * 256];
        }
        __syncthreads();   // weights + A tile (stage or prev epilogue) ready

        float acc[12][4];
        #pragma unroll
        for (int nt = 0; nt < 12; ++nt)
            #pragma unroll
            for (int r = 0; r < 4; ++r) acc[nt][r] = 0.f;

        #pragma unroll 1
        for (int s = 0; s < 3; ++s) {
            const uint32_t Abase = (s == 2) ? A_LO : A_HI;
            const uint32_t Bbase = sb + ((s == 1) ? B_LO : B_HI);
            #pragma unroll
            for (int ks = 0; ks < 4; ++ks) {
                const uint32_t kb = ks * 32;
                uint32_t a[4];
                LDSM_X4(a, a_rowbase + Abase + ((kb + akadd) ^ aswz));
                #pragma unroll
                for (int np = 0; np < 6; ++np) {
                    uint32_t b[4];
                    uint32_t baddr = Bbase + (uint32_t)(brow0 + np * 16) * 128
                                   + ((kb + bkadd) ^ bswz);
                    LDSM_X4(b, baddr);
                    mma16816(acc[2 * np],     a, b[0], b[1]);
                    mma16816(acc[2 * np + 1], a, b[2], b[3]);
                }
            }
        }

        // register gate epilogue: acc[3j]=i, acc[3j+1]=g, acc[3j+2]=o
        float hreg[4][4];
        const float* bl = bs + l * NW + n0 + 2 * tig;
        #pragma unroll
        for (int j = 0; j < 4; ++j) {
            float2 bi = *(const float2*)(bl + j * 24);
            float2 bg = *(const float2*)(bl + j * 24 + 8);
            float2 bo = *(const float2*)(bl + j * 24 + 16);
            const float* ai = acc[3 * j];
            const float* ag = acc[3 * j + 1];
            const float* ao = acc[3 * j + 2];
            hreg[j][0] = hsig(ao[0] + bo.x) * tanh_fast(hsig(ai[0] + bi.x) * tanh_fast(ag[0] + bg.x));
            hreg[j][1] = hsig(ao[1] + bo.y) * tanh_fast(hsig(ai[1] + bi.y) * tanh_fast(ag[1] + bg.y));
            hreg[j][2] = hsig(ao[2] + bo.x) * tanh_fast(hsig(ai[2] + bi.x) * tanh_fast(ag[2] + bg.x));
            hreg[j][3] = hsig(ao[3] + bo.y) * tanh_fast(hsig(ai[3] + bi.y) * tanh_fast(ag[3] + bg.y));
        }

        if (l < 3) {
            __syncthreads();   // all warps done reading A -> safe to overwrite
            #pragma unroll
            for (int j = 0; j < 4; ++j) {
                int c0 = chb + j * 8 + 2 * tig;
                uint32_t hi0 = pk2bf(hreg[j][0], hreg[j][1]);
                uint32_t hi1 = pk2bf(hreg[j][2], hreg[j][3]);
                float r00 = hreg[j][0] - __bfloat162float(__float2bfloat16(hreg[j][0]));
                float r01 = hreg[j][1] - __bfloat162float(__float2bfloat16(hreg[j][1]));
                float r10 = hreg[j][2] - __bfloat162float(__float2bfloat16(hreg[j][2]));
                float r11 = hreg[j][3] - __bfloat162float(__float2bfloat16(hreg[j][3]));
                uint32_t b1o = (uint32_t)m1 * 128 + (((uint32_t)(2 * c0)) ^ (((uint32_t)m1 & 7) << 4));
                uint32_t b2o = (uint32_t)m2 * 128 + (((uint32_t)(2 * c0)) ^ (((uint32_t)m2 & 7) << 4));
                *(uint32_t*)(sm + A_HI + b1o) = hi0;
                *(uint32_t*)(sm + A_LO + b1o) = pk2bf(r00, r01);
                *(uint32_t*)(sm + A_HI + b2o) = hi1;
                *(uint32_t*)(sm + A_LO + b2o) = pk2bf(r10, r11);
            }
        } else {
            #pragma unroll
            for (int j = 0; j < 4; ++j) {
                int c0 = chb + j * 8 + 2 * tig;
                *(float2*)&g_h4[(p0 + m1) * CH + c0] = make_float2(hreg[j][0], hreg[j][1]);
                *(float2*)&g_h4[(p0 + m2) * CH + c0] = make_float2(hreg[j][2], hreg[j][3]);
            }
        }
    }
}

// ---------------------------------------------------------------------------
// Kernel B: split-K GEMM  partial[g] = flat[:, kb:kb+128] @ D1w[kb:kb+128, :]
// ---------------------------------------------------------------------------
__global__ void __launch_bounds__(256) k_dense_split(const float* __restrict__ D1w)
{
    extern __shared__ float smf[];
    float* As  = smf;             // [64][128]
    float* Bsm = smf + 64 * KC;   // [128][64]
    const int tid = threadIdx.x;
    const size_t kbase = (size_t)blockIdx.x * KC;

    for (int i = tid; i < 64 * (KC / 4); i += 256) {
        int b = i / (KC / 4), kq = i % (KC / 4);
        ((float4*)As)[i] = *(const float4*)(g_h4 + (size_t)b * FLATK + kbase + (size_t)kq * 4);
    }
    {
        const float4* d1 = (const float4*)(D1w + kbase * 64);
        for (int i = tid; i < KC * 16; i += 256) ((float4*)Bsm)[i] = d1[i];
    }
    __syncthreads();

    const int tx = tid & 15, ty = tid >> 4;
    const int b0 = ty * 4, n0 = tx * 4;
    u64 acc[4][2] = {};
    #pragma unroll 4
    for (int k = 0; k < KC; ++k) {
        ulonglong2 bw = *(const ulonglong2*)&Bsm[k * 64 + n0];
        #pragma unroll
        for (int j = 0; j < 4; ++j) {
            float a = As[(b0 + j) * KC + k];
            u64 pa = pk2(a, a);
            acc[j][0] = ffma2(pa, bw.x, acc[j][0]);
            acc[j][1] = ffma2(pa, bw.y, acc[j][1]);
        }
    }
    float* dst = g_part + (size_t)blockIdx.x * 4096;
    #pragma unroll
    for (int j = 0; j < 4; ++j) {
        float a0, a1, a2, a3;
        upk2(acc[j][0], a0, a1);
        upk2(acc[j][1], a2, a3);
        *(float4*)&dst[(b0 + j) * 64 + n0] = make_float4(a0, a1, a2, a3);
    }
}

// ---------------------------------------------------------------------------
// Kernel C1: stage-1 reduce: 512 blocks, each sums 128 g-slices for (b,chunk).
// ---------------------------------------------------------------------------
__global__ void k_red1()
{
    __shared__ float sred[256];
    const int blk = blockIdx.x;            // 512 = 64 b x 8 chunks
    const int b = blk >> 3, chunk = blk & 7;
    const int tid = threadIdx.x;
    const int n = tid & 63, sub = tid >> 6;
    const float* p = g_part + (size_t)(chunk * 128 + sub * 32) * 4096 + (size_t)b * 64 + n;
    float s = 0.f;
    #pragma unroll 8
    for (int t = 0; t < 32; ++t) s += p[(size_t)t * 4096];
    sred[tid] = s;
    __syncthreads();
    if (tid < 64)
        g_red[chunk * 4096 + b * 64 + n] =
            sred[tid] + sred[tid + 64] + sred[tid + 128] + sred[tid + 192];
}

// ---------------------------------------------------------------------------
// Kernel C2: final: sum 8 chunks + D1b + relu + D2 GEMV. 64 blocks x 64 thr.
// ---------------------------------------------------------------------------
__global__ void k_final(const float* __restrict__ D1b, const float* __restrict__ D2w,
                        const float* __restrict__ D2b, float* __restrict__ out)
{
    __shared__ float sA[2];
    const int b = blockIdx.x, n = threadIdx.x;   // 64 threads
    float v = 0.f;
    #pragma unroll
    for (int ch = 0; ch < 8; ++ch) v += g_red[ch * 4096 + b * 64 + n];
    float y = fmaxf(v + D1b[n], 0.f) * D2w[n];
    #pragma unroll
    for (int off = 16; off > 0; off >>= 1)
        y += __shfl_down_sync(0xffffffffu, y, off);
    if ((n & 31) == 0) sA[n >> 5] = y;
    __syncthreads();
    if (n == 0) out[b] = sA[0] + sA[1] + D2b[0];
}

// ---------------------------------------------------------------------------
extern "C" void kernel_launch(void* const* d_in, const int* in_sizes, int n_in,
                              void* d_out, int out_size)
{
    const float* x   = (const float*)d_in[0];
    const float* W1x = (const float*)d_in[1];
    const float* b1  = (const float*)d_in[3];
    const float* W2x = (const float*)d_in[4];
    const float* b2  = (const float*)d_in[6];
    const float* W3x = (const float*)d_in[7];
    const float* b3  = (const float*)d_in[9];
    const float* W4x = (const float*)d_in[10];
    const float* b4  = (const float*)d_in[12];
    const float* D1w = (const float*)d_in[13];
    const float* D1b = (const float*)d_in[14];
    const float* D2w = (const float*)d_in[15];
    const float* D2b = (const float*)d_in[16];

    const int smemB = (64 * KC + KC * 64) * 4;   // 65536 B
    cudaFuncSetAttribute(k_lstm4, cudaFuncAttributeMaxDynamicSharedMemorySize, SMEM_A_TOT);
    cudaFuncSetAttribute(k_dense_split, cudaFuncAttributeMaxDynamicSharedMemorySize, smemB);

    // SAME padding over H=1 picks exactly one kernel row: r=4 (kh=10), r=2 (kh=5)
    k_prep<<<4, 256>>>(W1x + 4 * 64 * 256, W2x + 2 * 64 * 256,
                       W3x + 4 * 64 * 256, W4x + 2 * 64 * 256,
                       b1, b2, b3, b4);
    k_lstm4<<<NBLK_A, 256, SMEM_A_TOT>>>(x);
    k_dense_split<<<GSPLIT, 256, smemB>>>(D1w);
    k_red1<<<512, 256>>>();
    k_final<<<BATCH, 64>>>(D1b, D2w, D2b, (float*)d_out);
}

// round 7
// speedup vs baseline: 1.9845x; 1.0974x over previous
#include <cuda_runtime.h>
#include <cuda_bf16.h>
#include <cstdint>
#include <math.h>

#define BATCH 64
#define WPOS  2048
#define NPOS  (BATCH * WPOS)      // 131072 positions
#define CH    64
#define MTILE 128                 // positions per tile (kernel A)
#define NTILES (NPOS / MTILE)     // 1024
#define GRID_A 148                // persistent blocks (1/SM)
#define THR_A  512
#define KC    128                 // K chunk for dense split-K
#define FLATK (WPOS * CH)         // 131072
#define GSPLIT (FLATK / KC)       // 1024
#define NW    192                 // gates i,g,o (f gate dead)

// ---- scratch (device globals; no allocation allowed) -----------------------
__device__ __align__(16) float g_h4[(size_t)NPOS * CH];            // 32 MB
__device__ __align__(16) float g_part[(size_t)GSPLIT * 64 * 64];   // 16 MB
__device__ __align__(16) float g_red[8 * 64 * 64];                 // 128 KB
__device__ __align__(16) unsigned short g_Wsp[4][2][NW * 64];      // pre-swizzled bf16 hi/lo
__device__ __align__(16) float g_Bp[4][NW];

typedef unsigned long long u64;

__device__ __forceinline__ u64 pk2(float lo, float hi) {
    u64 r; asm("mov.b64 %0,{%1,%2};" : "=l"(r) : "f"(lo), "f"(hi)); return r;
}
__device__ __forceinline__ void upk2(u64 v, float& lo, float& hi) {
    asm("mov.b64 {%0,%1},%2;" : "=f"(lo), "=f"(hi) : "l"(v));
}
__device__ __forceinline__ u64 ffma2(u64 a, u64 b, u64 c) {
    u64 d; asm("fma.rn.f32x2 %0,%1,%2,%3;" : "=l"(d) : "l"(a), "l"(b), "l"(c)); return d;
}
__device__ __forceinline__ float hsig(float v) {
    return __saturatef(fmaf(v, 0.2f, 0.5f));
}
__device__ __forceinline__ float tanh_fast(float v) {   // MUFU.TANH, sm_75+
    float r; asm("tanh.approx.f32 %0,%1;" : "=f"(r) : "f"(v)); return r;
}
__device__ __forceinline__ uint32_t smem_u32(const void* p) {
    uint32_t a;
    asm("{ .reg .u64 t; cvta.to.shared.u64 t, %1; cvt.u32.u64 %0, t; }" : "=r"(a) : "l"(p));
    return a;
}

// warp-level mma + ldmatrix (plain sm_80+ PTX; tcgen05 is 'a'-gated -> unusable here)
__device__ __forceinline__ void mma16816(float* c, const uint32_t* a, uint32_t b0, uint32_t b1) {
    asm volatile(
        "mma.sync.aligned.m16n8k16.row.col.f32.bf16.bf16.f32 "
        "{%0,%1,%2,%3},{%4,%5,%6,%7},{%8,%9},{%0,%1,%2,%3};"
        : "+f"(c[0]), "+f"(c[1]), "+f"(c[2]), "+f"(c[3])
        : "r"(a[0]), "r"(a[1]), "r"(a[2]), "r"(a[3]), "r"(b0), "r"(b1));
}
#define LDSM_X4(r, a) \
    asm volatile("ldmatrix.sync.aligned.m8n8.x4.shared.b16 {%0,%1,%2,%3}, [%4];" \
        : "=r"((r)[0]), "=r"((r)[1]), "=r"((r)[2]), "=r"((r)[3]) : "r"(a))

__device__ __forceinline__ u64 pack4bf(float a, float b, float c, float d) {
    return (u64)__bfloat16_as_ushort(__float2bfloat16(a))
         | ((u64)__bfloat16_as_ushort(__float2bfloat16(b)) << 16)
         | ((u64)__bfloat16_as_ushort(__float2bfloat16(c)) << 32)
         | ((u64)__bfloat16_as_ushort(__float2bfloat16(d)) << 48);
}
__device__ __forceinline__ uint32_t pk2bf(float a, float b) {
    return (uint32_t)__bfloat16_as_ushort(__float2bfloat16(a))
         | ((uint32_t)__bfloat16_as_ushort(__float2bfloat16(b)) << 16);
}

// smem layout (bytes): all 4 layers' weights resident + A tiles + bias
#define WOFF   0                        // 4 x 49152 (hi 24576 | lo 24576 per layer)
#define WLSZ   49152
#define A_HI   (4 * WLSZ)               // 196608: [128 rows][64 bf16] XOR-swz, 16384 B
#define A_LO   (A_HI + 16384)           // 212992
#define BIAS   (A_LO + 16384)           // 229376: 4*192 f32
#define SMEM_A_TOT 232448               // == sm_103 opt-in max

// ---------------------------------------------------------------------------
// Prep: bf16 hi/lo split of the 4 weight slices, GATE-INTERLEAVED n-order:
//   n = half*96 + j*24 + gate*8 + e  ->  channel c = half*32 + j*8 + e
// XOR row swizzle pre-applied so blocks copy verbatim.
// ---------------------------------------------------------------------------
__global__ void k_prep(const float* __restrict__ W0, const float* __restrict__ W1,
                       const float* __restrict__ W2, const float* __restrict__ W3,
                       const float* __restrict__ B0, const float* __restrict__ B1,
                       const float* __restrict__ B2, const float* __restrict__ B3)
{
    const int l = blockIdx.x, tid = threadIdx.x;
    const float* W  = (l == 0) ? W0 : (l == 1) ? W1 : (l == 2) ? W2 : W3;
    const float* Bb = (l == 0) ? B0 : (l == 1) ? B1 : (l == 2) ? B2 : B3;
    for (int idx = tid; idx < NW * 64; idx += 256) {
        int n = idx >> 6, k = idx & 63;
        int half = n / 96, r = n % 96;
        int j = r / 24, gate = (r % 24) >> 3, e = r & 7;
        int c = half * 32 + j * 8 + e;
        int gn = (gate == 0) ? c : (gate == 1) ? 128 + c : 192 + c;   // skip dead f gate
        float w = W[k * 256 + gn];
        __nv_bfloat16 hb = __float2bfloat16(w);
        __nv_bfloat16 lb = __float2bfloat16(w - __bfloat162float(hb));
        uint32_t sw = (uint32_t)n * 64 + ((((uint32_t)(2 * k)) ^ (((uint32_t)n & 7) << 4)) >> 1);
        g_Wsp[l][0][sw] = __bfloat16_as_ushort(hb);
        g_Wsp[l][1][sw] = __bfloat16_as_ushort(lb);
    }
    for (int n = tid; n < NW; n += 256) {
        int half = n / 96, r = n % 96;
        int j = r / 24, gate = (r % 24) >> 3, e = r & 7;
        int c = half * 32 + j * 8 + e;
        int gn = (gate == 0) ? c : (gate == 1) ? 128 + c : 192 + c;
        g_Bp[l][n] = Bb[gn];
    }
}

// ---------------------------------------------------------------------------
// Kernel A: persistent fused 4x ConvLSTM via mma.sync bf16x3.
// 148 blocks x 512 threads; ALL 4 layers' weights resident in smem (loaded
// once). Each block loops over ~7 tiles of 128 positions. 16 warps, each
// [16m x 96n] gate-interleaved -> register epilogue with MUFU.TANH.
// ---------------------------------------------------------------------------
__global__ void __launch_bounds__(THR_A, 1) k_lstm4(const float* __restrict__ x)
{
    extern __shared__ char sm[];
    const uint32_t sb = smem_u32(sm);
    const int tid = threadIdx.x;
    const int wid = tid >> 5, lane = tid & 31;
    const int g8 = lane >> 2, tig = lane & 3;

    // one-time: weights (192KB) + biases -> smem
    {
        const uint4* src = (const uint4*)g_Wsp;
        uint4* dst = (uint4*)(sm + WOFF);
        #pragma unroll
        for (int i = 0; i < 24; ++i) dst[tid + i * THR_A] = src[tid + i * THR_A];
        float* bsw = (float*)(sm + BIAS);
        #pragma unroll
        for (int i = 0; i < 2; ++i) {
            int idx = tid + i * THR_A;
            if (idx < 4 * NW) bsw[idx] = ((const float*)g_Bp)[idx];
        }
    }
    const float* bs = (const float*)(sm + BIAS);

    // ldmatrix lane roles (16 warps: 8 m-tiles x 2 n-halves)
    const int lt = lane >> 3, lr = lane & 7;
    const int mrow = (wid & 7) * 16, half = wid >> 3;
    const int n0 = half * 96, chb = half * 32;
    const int arow = mrow + ((lt & 1) << 3) + lr;
    const uint32_t a_rowoff = (uint32_t)arow * 128;
    const uint32_t aswz = ((uint32_t)arow & 7) << 4;
    const int akadd = (lt >> 1) << 4;
    const int brow0 = n0 + ((lt >> 1) << 3) + lr;
    const uint32_t b_rowoff0 = (uint32_t)brow0 * 128;
    const uint32_t bswz = ((uint32_t)brow0 & 7) << 4;
    const int bkadd = (lt & 1) << 4;
    const int m1 = mrow + g8, m2 = m1 + 8;

    for (int t = blockIdx.x; t < NTILES; t += GRID_A) {
        __syncthreads();   // prev tile's layer-3 A reads done (and weights on iter 0)

        {   // stage input tile as bf16 hi/lo, XOR row swizzle
            const float4* xin = (const float4*)(x + (size_t)t * MTILE * CH);
            #pragma unroll
            for (int i = 0; i < 4; ++i) {
                int fi = tid + i * THR_A;               // 2048 float4
                int pos = fi >> 4, c = (fi & 15) << 2;
                float4 v = xin[fi];
                float h0 = __bfloat162float(__float2bfloat16(v.x));
                float h1 = __bfloat162float(__float2bfloat16(v.y));
                float h2 = __bfloat162float(__float2bfloat16(v.z));
                float h3 = __bfloat162float(__float2bfloat16(v.w));
                uint32_t b = (uint32_t)pos * 128 + (((uint32_t)(2 * c)) ^ (((uint32_t)pos & 7) << 4));
                *(u64*)(sm + A_HI + b) = pack4bf(v.x, v.y, v.z, v.w);
                *(u64*)(sm + A_LO + b) = pack4bf(v.x - h0, v.y - h1, v.z - h2, v.w - h3);
            }
        }
        __syncthreads();

        #pragma unroll 1
        for (int l = 0; l < 4; ++l) {
            float acc[12][4];
            #pragma unroll
            for (int nt = 0; nt < 12; ++nt)
                #pragma unroll
                for (int r = 0; r < 4; ++r) acc[nt][r] = 0.f;

            const uint32_t wbase = sb + WOFF + (uint32_t)l * WLSZ;
            #pragma unroll 1
            for (int s = 0; s < 3; ++s) {
                const uint32_t Aabs = sb + ((s == 2) ? A_LO : A_HI) + a_rowoff;
                const uint32_t Babs = wbase + ((s == 1) ? 24576u : 0u) + b_rowoff0;
                #pragma unroll
                for (int ks = 0; ks < 4; ++ks) {
                    const uint32_t kb = ks * 32;
                    uint32_t a[4];
                    LDSM_X4(a, Aabs + ((kb + akadd) ^ aswz));
                    #pragma unroll
                    for (int np = 0; np < 6; ++np) {
                        uint32_t b[4];
                        LDSM_X4(b, Babs + (uint32_t)np * 2048 + ((kb + bkadd) ^ bswz));
                        mma16816(acc[2 * np],     a, b[0], b[1]);
                        mma16816(acc[2 * np + 1], a, b[2], b[3]);
                    }
                }
            }

            // register gate epilogue: acc[3j]=i, acc[3j+1]=g, acc[3j+2]=o
            float hreg[4][4];
            const float* bl = bs + l * NW + n0 + 2 * tig;
            #pragma unroll
            for (int j = 0; j < 4; ++j) {
                float2 bi = *(const float2*)(bl + j * 24);
                float2 bg = *(const float2*)(bl + j * 24 + 8);
                float2 bo = *(const float2*)(bl + j * 24 + 16);
                const float* ai = acc[3 * j];
                const float* ag = acc[3 * j + 1];
                const float* ao = acc[3 * j + 2];
                hreg[j][0] = hsig(ao[0] + bo.x) * tanh_fast(hsig(ai[0] + bi.x) * tanh_fast(ag[0] + bg.x));
                hreg[j][1] = hsig(ao[1] + bo.y) * tanh_fast(hsig(ai[1] + bi.y) * tanh_fast(ag[1] + bg.y));
                hreg[j][2] = hsig(ao[2] + bo.x) * tanh_fast(hsig(ai[2] + bi.x) * tanh_fast(ag[2] + bg.x));
                hreg[j][3] = hsig(ao[3] + bo.y) * tanh_fast(hsig(ai[3] + bi.y) * tanh_fast(ag[3] + bg.y));
            }

            if (l < 3) {
                __syncthreads();   // all warps done reading A -> safe to overwrite
                #pragma unroll
                for (int j = 0; j < 4; ++j) {
                    int c0 = chb + j * 8 + 2 * tig;
                    float r00 = hreg[j][0] - __bfloat162float(__float2bfloat16(hreg[j][0]));
                    float r01 = hreg[j][1] - __bfloat162float(__float2bfloat16(hreg[j][1]));
                    float r10 = hreg[j][2] - __bfloat162float(__float2bfloat16(hreg[j][2]));
                    float r11 = hreg[j][3] - __bfloat162float(__float2bfloat16(hreg[j][3]));
                    uint32_t b1o = (uint32_t)m1 * 128 + (((uint32_t)(2 * c0)) ^ (((uint32_t)m1 & 7) << 4));
                    uint32_t b2o = (uint32_t)m2 * 128 + (((uint32_t)(2 * c0)) ^ (((uint32_t)m2 & 7) << 4));
                    *(uint32_t*)(sm + A_HI + b1o) = pk2bf(hreg[j][0], hreg[j][1]);
                    *(uint32_t*)(sm + A_LO + b1o) = pk2bf(r00, r01);
                    *(uint32_t*)(sm + A_HI + b2o) = pk2bf(hreg[j][2], hreg[j][3]);
                    *(uint32_t*)(sm + A_LO + b2o) = pk2bf(r10, r11);
                }
                __syncthreads();
            } else {
                const size_t p0 = (size_t)t * MTILE;
                #pragma unroll
                for (int j = 0; j < 4; ++j) {
                    int c0 = chb + j * 8 + 2 * tig;
                    *(float2*)&g_h4[(p0 + m1) * CH + c0] = make_float2(hreg[j][0], hreg[j][1]);
                    *(float2*)&g_h4[(p0 + m2) * CH + c0] = make_float2(hreg[j][2], hreg[j][3]);
                }
            }
        }
    }
}

// ---------------------------------------------------------------------------
// Kernel B: split-K GEMM  partial[g] = flat[:, kb:kb+128] @ D1w[kb:kb+128, :]
// ---------------------------------------------------------------------------
__global__ void __launch_bounds__(256) k_dense_split(const float* __restrict__ D1w)
{
    extern __shared__ float smf[];
    float* As  = smf;             // [64][128]
    float* Bsm = smf + 64 * KC;   // [128][64]
    const int tid = threadIdx.x;
    const size_t kbase = (size_t)blockIdx.x * KC;

    for (int i = tid; i < 64 * (KC / 4); i += 256) {
        int b = i / (KC / 4), kq = i % (KC / 4);
        ((float4*)As)[i] = *(const float4*)(g_h4 + (size_t)b * FLATK + kbase + (size_t)kq * 4);
    }
    {
        const float4* d1 = (const float4*)(D1w + kbase * 64);
        for (int i = tid; i < KC * 16; i += 256) ((float4*)Bsm)[i] = d1[i];
    }
    __syncthreads();

    const int tx = tid & 15, ty = tid >> 4;
    const int b0 = ty * 4, n0 = tx * 4;
    u64 acc[4][2] = {};
    #pragma unroll 4
    for (int k = 0; k < KC; ++k) {
        ulonglong2 bw = *(const ulonglong2*)&Bsm[k * 64 + n0];
        #pragma unroll
        for (int j = 0; j < 4; ++j) {
            float a = As[(b0 + j) * KC + k];
            u64 pa = pk2(a, a);
            acc[j][0] = ffma2(pa, bw.x, acc[j][0]);
            acc[j][1] = ffma2(pa, bw.y, acc[j][1]);
        }
    }
    float* dst = g_part + (size_t)blockIdx.x * 4096;
    #pragma unroll
    for (int j = 0; j < 4; ++j) {
        float a0, a1, a2, a3;
        upk2(acc[j][0], a0, a1);
        upk2(acc[j][1], a2, a3);
        *(float4*)&dst[(b0 + j) * 64 + n0] = make_float4(a0, a1, a2, a3);
    }
}

// ---------------------------------------------------------------------------
// Kernel C1: stage-1 reduce: 512 blocks, each sums 128 g-slices for (b,chunk).
// ---------------------------------------------------------------------------
__global__ void k_red1()
{
    __shared__ float sred[256];
    const int blk = blockIdx.x;            // 512 = 64 b x 8 chunks
    const int b = blk >> 3, chunk = blk & 7;
    const int tid = threadIdx.x;
    const int n = tid & 63, sub = tid >> 6;
    const float* p = g_part + (size_t)(chunk * 128 + sub * 32) * 4096 + (size_t)b * 64 + n;
    float s = 0.f;
    #pragma unroll 8
    for (int t = 0; t < 32; ++t) s += p[(size_t)t * 4096];
    sred[tid] = s;
    __syncthreads();
    if (tid < 64)
        g_red[chunk * 4096 + b * 64 + n] =
            sred[tid] + sred[tid + 64] + sred[tid + 128] + sred[tid + 192];
}

// ---------------------------------------------------------------------------
// Kernel C2: final: sum 8 chunks + D1b + relu + D2 GEMV. 64 blocks x 64 thr.
// ---------------------------------------------------------------------------
__global__ void k_final(const float* __restrict__ D1b, const float* __restrict__ D2w,
                        const float* __restrict__ D2b, float* __restrict__ out)
{
    __shared__ float sA[2];
    const int b = blockIdx.x, n = threadIdx.x;   // 64 threads
    float v = 0.f;
    #pragma unroll
    for (int ch = 0; ch < 8; ++ch) v += g_red[ch * 4096 + b * 64 + n];
    float y = fmaxf(v + D1b[n], 0.f) * D2w[n];
    #pragma unroll
    for (int off = 16; off > 0; off >>= 1)
        y += __shfl_down_sync(0xffffffffu, y, off);
    if ((n & 31) == 0) sA[n >> 5] = y;
    __syncthreads();
    if (n == 0) out[b] = sA[0] + sA[1] + D2b[0];
}

// ---------------------------------------------------------------------------
extern "C" void kernel_launch(void* const* d_in, const int* in_sizes, int n_in,
                              void* d_out, int out_size)
{
    const float* x   = (const float*)d_in[0];
    const float* W1x = (const float*)d_in[1];
    const float* b1  = (const float*)d_in[3];
    const float* W2x = (const float*)d_in[4];
    const float* b2  = (const float*)d_in[6];
    const float* W3x = (const float*)d_in[7];
    const float* b3  = (const float*)d_in[9];
    const float* W4x = (const float*)d_in[10];
    const float* b4  = (const float*)d_in[12];
    const float* D1w = (const float*)d_in[13];
    const float* D1b = (const float*)d_in[14];
    const float* D2w = (const float*)d_in[15];
    const float* D2b = (const float*)d_in[16];

    const int smemB = (64 * KC + KC * 64) * 4;   // 65536 B
    cudaFuncSetAttribute(k_lstm4, cudaFuncAttributeMaxDynamicSharedMemorySize, SMEM_A_TOT);
    cudaFuncSetAttribute(k_dense_split, cudaFuncAttributeMaxDynamicSharedMemorySize, smemB);

    // SAME padding over H=1 picks exactly one kernel row: r=4 (kh=10), r=2 (kh=5)
    k_prep<<<4, 256>>>(W1x + 4 * 64 * 256, W2x + 2 * 64 * 256,
                       W3x + 4 * 64 * 256, W4x + 2 * 64 * 256,
                       b1, b2, b3, b4);
    k_lstm4<<<GRID_A, THR_A, SMEM_A_TOT>>>(x);
    k_dense_split<<<GSPLIT, 256, smemB>>>(D1w);
    k_red1<<<512, 256>>>();
    k_final<<<BATCH, 64>>>(D1b, D2w, D2b, (float*)d_out);
}

// round 8
// speedup vs baseline: 2.1176x; 1.0670x over previous
#include <cuda_runtime.h>
#include <cuda_bf16.h>
#include <cstdint>
#include <math.h>

#define BATCH 64
#define WPOS  2048
#define NPOS  (BATCH * WPOS)      // 131072 positions
#define CH    64
#define MTILE 64                  // positions per tile (kernel A)
#define NTILES (NPOS / MTILE)     // 2048
#define GRID_A 148                // persistent blocks (1/SM)
#define THR_A  512                // 2 groups x 256
#define KC    128                 // K chunk for dense split-K
#define FLATK (WPOS * CH)         // 131072
#define GSPLIT (FLATK / KC)       // 1024
#define NW    192                 // gates i,g,o (f gate dead)
#define RCH   32                  // red1 chunks

// ---- scratch (device globals; no allocation allowed) -----------------------
__device__ __align__(16) float g_h4[(size_t)NPOS * CH];            // 32 MB
__device__ __align__(16) float g_part[(size_t)GSPLIT * 64 * 64];   // 16 MB
__device__ __align__(16) float g_red[RCH * 64 * 64];               // 512 KB
__device__ __align__(16) unsigned short g_Wsp[4][2][NW * 64];      // pre-swizzled bf16 hi/lo
__device__ __align__(16) float g_Bp[4][NW];

typedef unsigned long long u64;

__device__ __forceinline__ u64 pk2(float lo, float hi) {
    u64 r; asm("mov.b64 %0,{%1,%2};" : "=l"(r) : "f"(lo), "f"(hi)); return r;
}
__device__ __forceinline__ void upk2(u64 v, float& lo, float& hi) {
    asm("mov.b64 {%0,%1},%2;" : "=f"(lo), "=f"(hi) : "l"(v));
}
__device__ __forceinline__ u64 ffma2(u64 a, u64 b, u64 c) {
    u64 d; asm("fma.rn.f32x2 %0,%1,%2,%3;" : "=l"(d) : "l"(a), "l"(b), "l"(c)); return d;
}
__device__ __forceinline__ float hsig(float v) {
    return __saturatef(fmaf(v, 0.2f, 0.5f));
}
__device__ __forceinline__ float tanh_fast(float v) {   // MUFU.TANH, sm_75+
    float r; asm("tanh.approx.f32 %0,%1;" : "=f"(r) : "f"(v)); return r;
}
__device__ __forceinline__ uint32_t smem_u32(const void* p) {
    uint32_t a;
    asm("{ .reg .u64 t; cvta.to.shared.u64 t, %1; cvt.u32.u64 %0, t; }" : "=r"(a) : "l"(p));
    return a;
}
#define GBAR(id) asm volatile("bar.sync %0, 256;" :: "r"(id) : "memory")

// warp-level mma + ldmatrix (plain sm_80+ PTX; tcgen05 is 'a'-gated -> unusable here)
__device__ __forceinline__ void mma16816(float* c, const uint32_t* a, uint32_t b0, uint32_t b1) {
    asm volatile(
        "mma.sync.aligned.m16n8k16.row.col.f32.bf16.bf16.f32 "
        "{%0,%1,%2,%3},{%4,%5,%6,%7},{%8,%9},{%0,%1,%2,%3};"
        : "+f"(c[0]), "+f"(c[1]), "+f"(c[2]), "+f"(c[3])
        : "r"(a[0]), "r"(a[1]), "r"(a[2]), "r"(a[3]), "r"(b0), "r"(b1));
}
#define LDSM_X4(r, a) \
    asm volatile("ldmatrix.sync.aligned.m8n8.x4.shared.b16 {%0,%1,%2,%3}, [%4];" \
        : "=r"((r)[0]), "=r"((r)[1]), "=r"((r)[2]), "=r"((r)[3]) : "r"(a))

__device__ __forceinline__ u64 pack4bf(float a, float b, float c, float d) {
    return (u64)__bfloat16_as_ushort(__float2bfloat16(a))
         | ((u64)__bfloat16_as_ushort(__float2bfloat16(b)) << 16)
         | ((u64)__bfloat16_as_ushort(__float2bfloat16(c)) << 32)
         | ((u64)__bfloat16_as_ushort(__float2bfloat16(d)) << 48);
}
__device__ __forceinline__ uint32_t pk2bf(float a, float b) {
    return (uint32_t)__bfloat16_as_ushort(__float2bfloat16(a))
         | ((uint32_t)__bfloat16_as_ushort(__float2bfloat16(b)) << 16);
}

// smem layout (bytes): 4 layers' weights resident + per-group A tiles + bias
#define WOFF   0                        // 4 x 49152 (hi 24576 | lo 24576 per layer)
#define WLSZ   49152
#define ABUF0  (4 * WLSZ)               // 196608: group0 A_HI(8K) + A_LO(8K)
#define ABUF1  (ABUF0 + 16384)          // 212992: group1
#define ABSZ   8192
#define BIAS   (ABUF1 + 16384)          // 229376: 4*192 f32
#define SMEM_A_TOT 232448               // == sm_103 opt-in max

// ---------------------------------------------------------------------------
// Prep: bf16 hi/lo split of the 4 weight slices, GATE-INTERLEAVED n-order:
//   n = half*96 + j*24 + gate*8 + e  ->  channel c = half*32 + j*8 + e
// XOR row swizzle pre-applied so blocks copy verbatim.
// ---------------------------------------------------------------------------
__global__ void k_prep(const float* __restrict__ W0, const float* __restrict__ W1,
                       const float* __restrict__ W2, const float* __restrict__ W3,
                       const float* __restrict__ B0, const float* __restrict__ B1,
                       const float* __restrict__ B2, const float* __restrict__ B3)
{
    const int l = blockIdx.x, tid = threadIdx.x;
    const float* W  = (l == 0) ? W0 : (l == 1) ? W1 : (l == 2) ? W2 : W3;
    const float* Bb = (l == 0) ? B0 : (l == 1) ? B1 : (l == 2) ? B2 : B3;
    for (int idx = tid; idx < NW * 64; idx += 256) {
        int n = idx >> 6, k = idx & 63;
        int half = n / 96, r = n % 96;
        int j = r / 24, gate = (r % 24) >> 3, e = r & 7;
        int c = half * 32 + j * 8 + e;
        int gn = (gate == 0) ? c : (gate == 1) ? 128 + c : 192 + c;   // skip dead f gate
        float w = W[k * 256 + gn];
        __nv_bfloat16 hb = __float2bfloat16(w);
        __nv_bfloat16 lb = __float2bfloat16(w - __bfloat162float(hb));
        uint32_t sw = (uint32_t)n * 64 + ((((uint32_t)(2 * k)) ^ (((uint32_t)n & 7) << 4)) >> 1);
        g_Wsp[l][0][sw] = __bfloat16_as_ushort(hb);
        g_Wsp[l][1][sw] = __bfloat16_as_ushort(lb);
    }
    for (int n = tid; n < NW; n += 256) {
        int half = n / 96, r = n % 96;
        int j = r / 24, gate = (r % 24) >> 3, e = r & 7;
        int c = half * 32 + j * 8 + e;
        int gn = (gate == 0) ? c : (gate == 1) ? 128 + c : 192 + c;
        g_Bp[l][n] = Bb[gn];
    }
}

// ---------------------------------------------------------------------------
// Kernel A: persistent fused 4x ConvLSTM via mma.sync bf16x3.
// 148 blocks x 512 threads = TWO independent 8-warp pipelines per block,
// synchronized by named barriers (ids 1,2), sharing the resident 192KB of
// weights. Each pipeline: 64-position tiles, warps [16m x 96n],
// gate-interleaved columns -> register epilogue with MUFU.TANH.
// ---------------------------------------------------------------------------
__global__ void __launch_bounds__(THR_A, 1) k_lstm4(const float* __restrict__ x)
{
    extern __shared__ char sm[];
    const uint32_t sb = smem_u32(sm);
    const int tid = threadIdx.x;
    const int wid = tid >> 5, lane = tid & 31;
    const int grp = tid >> 8;            // barrier group 0/1
    const int tig256 = tid & 255;        // tid within group
    const int g8 = lane >> 2, tig = lane & 3;

    // one-time: weights (192KB) + biases -> smem (all 512 threads)
    {
        const uint4* src = (const uint4*)g_Wsp;
        uint4* dst = (uint4*)(sm + WOFF);
        #pragma unroll
        for (int i = 0; i < 24; ++i) dst[tid + i * THR_A] = src[tid + i * THR_A];
        float* bsw = (float*)(sm + BIAS);
        #pragma unroll
        for (int i = 0; i < 2; ++i) {
            int idx = tid + i * THR_A;
            if (idx < 4 * NW) bsw[idx] = ((const float*)g_Bp)[idx];
        }
    }
    __syncthreads();                     // weights immutable hereafter
    const float* bs = (const float*)(sm + BIAS);

    // group-local warp layout: 8 warps = 4 m-tiles x 2 n-halves
    const int wg = wid & 7;
    const int lt = lane >> 3, lr = lane & 7;
    const int mrow = (wg & 3) * 16, half = wg >> 2;
    const int n0 = half * 96, chb = half * 32;
    const uint32_t AHI = ABUF0 + (uint32_t)grp * 16384;
    const uint32_t ALO = AHI + ABSZ;
    const int arow = mrow + ((lt & 1) << 3) + lr;
    const uint32_t a_rowoff = (uint32_t)arow * 128;
    const uint32_t aswz = ((uint32_t)arow & 7) << 4;
    const int akadd = (lt >> 1) << 4;
    const int brow0 = n0 + ((lt >> 1) << 3) + lr;
    const uint32_t b_rowoff0 = (uint32_t)brow0 * 128;
    const uint32_t bswz = ((uint32_t)brow0 & 7) << 4;
    const int bkadd = (lt & 1) << 4;
    const int m1 = mrow + g8, m2 = m1 + 8;
    const int bar = grp + 1;

    for (int t = blockIdx.x * 2 + grp; t < NTILES; t += GRID_A * 2) {
        GBAR(bar);   // prev tile's layer-3 A reads done

        {   // stage input tile as bf16 hi/lo, XOR row swizzle (256 thr, 1024 f4)
            const float4* xin = (const float4*)(x + (size_t)t * MTILE * CH);
            #pragma unroll
            for (int i = 0; i < 4; ++i) {
                int fi = tig256 + i * 256;
                int pos = fi >> 4, c = (fi & 15) << 2;
                float4 v = xin[fi];
                float h0 = __bfloat162float(__float2bfloat16(v.x));
                float h1 = __bfloat162float(__float2bfloat16(v.y));
                float h2 = __bfloat162float(__float2bfloat16(v.z));
                float h3 = __bfloat162float(__float2bfloat16(v.w));
                uint32_t b = (uint32_t)pos * 128 + (((uint32_t)(2 * c)) ^ (((uint32_t)pos & 7) << 4));
                *(u64*)(sm + AHI + b) = pack4bf(v.x, v.y, v.z, v.w);
                *(u64*)(sm + ALO + b) = pack4bf(v.x - h0, v.y - h1, v.z - h2, v.w - h3);
            }
        }
        GBAR(bar);

        #pragma unroll 1
        for (int l = 0; l < 4; ++l) {
            float acc[12][4];
            #pragma unroll
            for (int nt = 0; nt < 12; ++nt)
                #pragma unroll
                for (int r = 0; r < 4; ++r) acc[nt][r] = 0.f;

            const uint32_t wbase = sb + WOFF + (uint32_t)l * WLSZ;
            #pragma unroll 1
            for (int s = 0; s < 3; ++s) {
                const uint32_t Aabs = sb + ((s == 2) ? ALO : AHI) + a_rowoff;
                const uint32_t Babs = wbase + ((s == 1) ? 24576u : 0u) + b_rowoff0;
                #pragma unroll
                for (int ks = 0; ks < 4; ++ks) {
                    const uint32_t kb = ks * 32;
                    uint32_t a[4];
                    LDSM_X4(a, Aabs + ((kb + akadd) ^ aswz));
                    #pragma unroll
                    for (int np = 0; np < 6; ++np) {
                        uint32_t b[4];
                        LDSM_X4(b, Babs + (uint32_t)np * 2048 + ((kb + bkadd) ^ bswz));
                        mma16816(acc[2 * np],     a, b[0], b[1]);
                        mma16816(acc[2 * np + 1], a, b[2], b[3]);
                    }
                }
            }

            // register gate epilogue: acc[3j]=i, acc[3j+1]=g, acc[3j+2]=o
            float hreg[4][4];
            const float* bl = bs + l * NW + n0 + 2 * tig;
            #pragma unroll
            for (int j = 0; j < 4; ++j) {
                float2 bi = *(const float2*)(bl + j * 24);
                float2 bg = *(const float2*)(bl + j * 24 + 8);
                float2 bo = *(const float2*)(bl + j * 24 + 16);
                const float* ai = acc[3 * j];
                const float* ag = acc[3 * j + 1];
                const float* ao = acc[3 * j + 2];
                hreg[j][0] = hsig(ao[0] + bo.x) * tanh_fast(hsig(ai[0] + bi.x) * tanh_fast(ag[0] + bg.x));
                hreg[j][1] = hsig(ao[1] + bo.y) * tanh_fast(hsig(ai[1] + bi.y) * tanh_fast(ag[1] + bg.y));
                hreg[j][2] = hsig(ao[2] + bo.x) * tanh_fast(hsig(ai[2] + bi.x) * tanh_fast(ag[2] + bg.x));
                hreg[j][3] = hsig(ao[3] + bo.y) * tanh_fast(hsig(ai[3] + bi.y) * tanh_fast(ag[3] + bg.y));
            }

            if (l < 3) {
                GBAR(bar);   // group's warps done reading A -> safe to overwrite
                #pragma unroll
                for (int j = 0; j < 4; ++j) {
                    int c0 = chb + j * 8 + 2 * tig;
                    float r00 = hreg[j][0] - __bfloat162float(__float2bfloat16(hreg[j][0]));
                    float r01 = hreg[j][1] - __bfloat162float(__float2bfloat16(hreg[j][1]));
                    float r10 = hreg[j][2] - __bfloat162float(__float2bfloat16(hreg[j][2]));
                    float r11 = hreg[j][3] - __bfloat162float(__float2bfloat16(hreg[j][3]));
                    uint32_t b1o = (uint32_t)m1 * 128 + (((uint32_t)(2 * c0)) ^ (((uint32_t)m1 & 7) << 4));
                    uint32_t b2o = (uint32_t)m2 * 128 + (((uint32_t)(2 * c0)) ^ (((uint32_t)m2 & 7) << 4));
                    *(uint32_t*)(sm + AHI + b1o) = pk2bf(hreg[j][0], hreg[j][1]);
                    *(uint32_t*)(sm + ALO + b1o) = pk2bf(r00, r01);
                    *(uint32_t*)(sm + AHI + b2o) = pk2bf(hreg[j][2], hreg[j][3]);
                    *(uint32_t*)(sm + ALO + b2o) = pk2bf(r10, r11);
                }
                GBAR(bar);
            } else {
                const size_t p0 = (size_t)t * MTILE;
                #pragma unroll
                for (int j = 0; j < 4; ++j) {
                    int c0 = chb + j * 8 + 2 * tig;
                    *(float2*)&g_h4[(p0 + m1) * CH + c0] = make_float2(hreg[j][0], hreg[j][1]);
                    *(float2*)&g_h4[(p0 + m2) * CH + c0] = make_float2(hreg[j][2], hreg[j][3]);
                }
            }
        }
    }
}

// ---------------------------------------------------------------------------
// Kernel B: split-K GEMM  partial[g] = flat[:, kb:kb+128] @ D1w[kb:kb+128, :]
// ---------------------------------------------------------------------------
__global__ void __launch_bounds__(256) k_dense_split(const float* __restrict__ D1w)
{
    extern __shared__ float smf[];
    float* As  = smf;             // [64][128]
    float* Bsm = smf + 64 * KC;   // [128][64]
    const int tid = threadIdx.x;
    const size_t kbase = (size_t)blockIdx.x * KC;

    for (int i = tid; i < 64 * (KC / 4); i += 256) {
        int b = i / (KC / 4), kq = i % (KC / 4);
        ((float4*)As)[i] = *(const float4*)(g_h4 + (size_t)b * FLATK + kbase + (size_t)kq * 4);
    }
    {
        const float4* d1 = (const float4*)(D1w + kbase * 64);
        for (int i = tid; i < KC * 16; i += 256) ((float4*)Bsm)[i] = d1[i];
    }
    __syncthreads();

    const int tx = tid & 15, ty = tid >> 4;
    const int b0 = ty * 4, n0 = tx * 4;
    u64 acc[4][2] = {};
    #pragma unroll 4
    for (int k = 0; k < KC; ++k) {
        ulonglong2 bw = *(const ulonglong2*)&Bsm[k * 64 + n0];
        #pragma unroll
        for (int j = 0; j < 4; ++j) {
            float a = As[(b0 + j) * KC + k];
            u64 pa = pk2(a, a);
            acc[j][0] = ffma2(pa, bw.x, acc[j][0]);
            acc[j][1] = ffma2(pa, bw.y, acc[j][1]);
        }
    }
    float* dst = g_part + (size_t)blockIdx.x * 4096;
    #pragma unroll
    for (int j = 0; j < 4; ++j) {
        float a0, a1, a2, a3;
        upk2(acc[j][0], a0, a1);
        upk2(acc[j][1], a2, a3);
        *(float4*)&dst[(b0 + j) * 64 + n0] = make_float4(a0, a1, a2, a3);
    }
}

// ---------------------------------------------------------------------------
// Kernel C1: stage-1 reduce: 2048 blocks, each sums 32 g-slices for (b,chunk).
// ---------------------------------------------------------------------------
__global__ void k_red1()
{
    __shared__ float sred[256];
    const int blk = blockIdx.x;            // 2048 = 64 b x 32 chunks
    const int b = blk >> 5, chunk = blk & 31;
    const int tid = threadIdx.x;
    const int n = tid & 63, sub = tid >> 6;
    const float* p = g_part + (size_t)(chunk * 32 + sub * 8) * 4096 + (size_t)b * 64 + n;
    float s = 0.f;
    #pragma unroll
    for (int t = 0; t < 8; ++t) s += p[(size_t)t * 4096];
    sred[tid] = s;
    __syncthreads();
    if (tid < 64)
        g_red[chunk * 4096 + b * 64 + n] =
            sred[tid] + sred[tid + 64] + sred[tid + 128] + sred[tid + 192];
}

// ---------------------------------------------------------------------------
// Kernel C2: final: sum 32 chunks + D1b + relu + D2 GEMV. 64 blocks x 64 thr.
// ---------------------------------------------------------------------------
__global__ void k_final(const float* __restrict__ D1b, const float* __restrict__ D2w,
                        const float* __restrict__ D2b, float* __restrict__ out)
{
    __shared__ float sA[2];
    const int b = blockIdx.x, n = threadIdx.x;   // 64 threads
    float v = 0.f;
    #pragma unroll
    for (int ch = 0; ch < RCH; ++ch) v += g_red[ch * 4096 + b * 64 + n];
    float y = fmaxf(v + D1b[n], 0.f) * D2w[n];
    #pragma unroll
    for (int off = 16; off > 0; off >>= 1)
        y += __shfl_down_sync(0xffffffffu, y, off);
    if ((n & 31) == 0) sA[n >> 5] = y;
    __syncthreads();
    if (n == 0) out[b] = sA[0] + sA[1] + D2b[0];
}

// ---------------------------------------------------------------------------
extern "C" void kernel_launch(void* const* d_in, const int* in_sizes, int n_in,
                              void* d_out, int out_size)
{
    const float* x   = (const float*)d_in[0];
    const float* W1x = (const float*)d_in[1];
    const float* b1  = (const float*)d_in[3];
    const float* W2x = (const float*)d_in[4];
    const float* b2  = (const float*)d_in[6];
    const float* W3x = (const float*)d_in[7];
    const float* b3  = (const float*)d_in[9];
    const float* W4x = (const float*)d_in[10];
    const float* b4  = (const float*)d_in[12];
    const float* D1w = (const float*)d_in[13];
    const float* D1b = (const float*)d_in[14];
    const float* D2w = (const float*)d_in[15];
    const float* D2b = (const float*)d_in[16];

    const int smemB = (64 * KC + KC * 64) * 4;   // 65536 B
    cudaFuncSetAttribute(k_lstm4, cudaFuncAttributeMaxDynamicSharedMemorySize, SMEM_A_TOT);
    cudaFuncSetAttribute(k_dense_split, cudaFuncAttributeMaxDynamicSharedMemorySize, smemB);

    // SAME padding over H=1 picks exactly one kernel row: r=4 (kh=10), r=2 (kh=5)
    k_prep<<<4, 256>>>(W1x + 4 * 64 * 256, W2x + 2 * 64 * 256,
                       W3x + 4 * 64 * 256, W4x + 2 * 64 * 256,
                       b1, b2, b3, b4);
    k_lstm4<<<GRID_A, THR_A, SMEM_A_TOT>>>(x);
    k_dense_split<<<GSPLIT, 256, smemB>>>(D1w);
    k_red1<<<2048, 256>>>();
    k_final<<<BATCH, 64>>>(D1b, D2w, D2b, (float*)d_out);
}

// round 9
// speedup vs baseline: 2.4690x; 1.1660x over previous
#include <cuda_runtime.h>
#include <cuda_fp16.h>
#include <cstdint>
#include <math.h>

#define BATCH 64
#define WPOS  2048
#define NPOS  (BATCH * WPOS)      // 131072 positions
#define CH    64
#define MTILE 64                  // positions per tile (kernel A)
#define NTILES (NPOS / MTILE)     // 2048
#define GRID_A 148                // persistent blocks (1/SM)
#define THR_A  512                // 2 groups x 256
#define KC    128                 // K chunk for dense split-K
#define FLATK (WPOS * CH)         // 131072
#define GSPLIT (FLATK / KC)       // 1024
#define NW    192                 // gates i,g,o (f gate dead)
#define RCH   32                  // red1 chunks

// ---- scratch (device globals; no allocation allowed) -----------------------
__device__ __align__(16) float g_h4[(size_t)NPOS * CH];            // 32 MB
__device__ __align__(16) float g_part[(size_t)GSPLIT * 64 * 64];   // 16 MB
__device__ __align__(16) float g_red[RCH * 64 * 64];               // 512 KB
__device__ __align__(16) unsigned short g_Wh[4][NW * 64];          // pre-swizzled fp16 weights
__device__ __align__(16) float g_Bp[4][NW];

typedef unsigned long long u64;

__device__ __forceinline__ u64 pk2(float lo, float hi) {
    u64 r; asm("mov.b64 %0,{%1,%2};" : "=l"(r) : "f"(lo), "f"(hi)); return r;
}
__device__ __forceinline__ void upk2(u64 v, float& lo, float& hi) {
    asm("mov.b64 {%0,%1},%2;" : "=f"(lo), "=f"(hi) : "l"(v));
}
__device__ __forceinline__ u64 ffma2(u64 a, u64 b, u64 c) {
    u64 d; asm("fma.rn.f32x2 %0,%1,%2,%3;" : "=l"(d) : "l"(a), "l"(b), "l"(c)); return d;
}
__device__ __forceinline__ float hsig(float v) {
    return __saturatef(fmaf(v, 0.2f, 0.5f));
}
__device__ __forceinline__ float tanh_fast(float v) {   // MUFU.TANH, sm_75+
    float r; asm("tanh.approx.f32 %0,%1;" : "=f"(r) : "f"(v)); return r;
}
__device__ __forceinline__ uint32_t smem_u32(const void* p) {
    uint32_t a;
    asm("{ .reg .u64 t; cvta.to.shared.u64 t, %1; cvt.u32.u64 %0, t; }" : "=r"(a) : "l"(p));
    return a;
}
#define GBAR(id) asm volatile("bar.sync %0, 256;" :: "r"(id) : "memory")

// warp-level fp16 mma + ldmatrix (plain sm_80+ PTX; tcgen05 is 'a'-gated)
__device__ __forceinline__ void mma16816(float* c, const uint32_t* a, uint32_t b0, uint32_t b1) {
    asm volatile(
        "mma.sync.aligned.m16n8k16.row.col.f32.f16.f16.f32 "
        "{%0,%1,%2,%3},{%4,%5,%6,%7},{%8,%9},{%0,%1,%2,%3};"
        : "+f"(c[0]), "+f"(c[1]), "+f"(c[2]), "+f"(c[3])
        : "r"(a[0]), "r"(a[1]), "r"(a[2]), "r"(a[3]), "r"(b0), "r"(b1));
}
#define LDSM_X4(r, a) \
    asm volatile("ldmatrix.sync.aligned.m8n8.x4.shared.b16 {%0,%1,%2,%3}, [%4];" \
        : "=r"((r)[0]), "=r"((r)[1]), "=r"((r)[2]), "=r"((r)[3]) : "r"(a))

__device__ __forceinline__ unsigned short f2h(float a) {
    return __half_as_ushort(__float2half_rn(a));
}
__device__ __forceinline__ float h2f(unsigned short a) {
    return __half2float(__ushort_as_half(a));
}
__device__ __forceinline__ u64 pack4hf(float a, float b, float c, float d) {
    return (u64)f2h(a) | ((u64)f2h(b) << 16) | ((u64)f2h(c) << 32) | ((u64)f2h(d) << 48);
}
__device__ __forceinline__ uint32_t pk2hf(float a, float b) {
    return (uint32_t)f2h(a) | ((uint32_t)f2h(b) << 16);
}

// smem layout (bytes): 4 fp16 weight images + 2 groups x 2 ping-pong A bufs + bias
#define WOFF   0                        // 4 x 24576 fp16 [192n][64k] XOR-swz
#define WLSZ   24576
#define ABUF   (4 * WLSZ)               // 98304: grp stride 32768, buf stride 16384
#define BIAS   (ABUF + 65536)           // 163840: 4*192 f32
#define SMEM_A_TOT 166912

// ---------------------------------------------------------------------------
// Prep: fp16 weight slices, GATE-INTERLEAVED n-order:
//   n = half*96 + j*24 + gate*8 + e  ->  channel c = half*32 + j*8 + e
// XOR row swizzle pre-applied so blocks copy verbatim.
// ---------------------------------------------------------------------------
__global__ void k_prep(const float* __restrict__ W0, const float* __restrict__ W1,
                       const float* __restrict__ W2, const float* __restrict__ W3,
                       const float* __restrict__ B0, const float* __restrict__ B1,
                       const float* __restrict__ B2, const float* __restrict__ B3)
{
    const int l = blockIdx.x, tid = threadIdx.x;
    const float* W  = (l == 0) ? W0 : (l == 1) ? W1 : (l == 2) ? W2 : W3;
    const float* Bb = (l == 0) ? B0 : (l == 1) ? B1 : (l == 2) ? B2 : B3;
    for (int idx = tid; idx < NW * 64; idx += 256) {
        int n = idx >> 6, k = idx & 63;
        int half = n / 96, r = n % 96;
        int j = r / 24, gate = (r % 24) >> 3, e = r & 7;
        int c = half * 32 + j * 8 + e;
        int gn = (gate == 0) ? c : (gate == 1) ? 128 + c : 192 + c;   // skip dead f gate
        uint32_t sw = (uint32_t)n * 64 + ((((uint32_t)(2 * k)) ^ (((uint32_t)n & 7) << 4)) >> 1);
        g_Wh[l][sw] = f2h(W[k * 256 + gn]);
    }
    for (int n = tid; n < NW; n += 256) {
        int half = n / 96, r = n % 96;
        int j = r / 24, gate = (r % 24) >> 3, e = r & 7;
        int c = half * 32 + j * 8 + e;
        int gn = (gate == 0) ? c : (gate == 1) ? 128 + c : 192 + c;
        g_Bp[l][n] = Bb[gn];
    }
}

// ---------------------------------------------------------------------------
// Kernel A: persistent fused 4x ConvLSTM via mma.sync fp16 2-pass
// (A split hi+lo fp16 -> near-exact activations; weights single fp16).
// 148 blocks x 512 threads = two independent 8-warp pipelines (named barriers),
// ping-pong A buffers -> 4 barriers/tile; register gate epilogue, MUFU.TANH.
// ---------------------------------------------------------------------------
__global__ void __launch_bounds__(THR_A, 1) k_lstm4(const float* __restrict__ x)
{
    extern __shared__ char sm[];
    const uint32_t sb = smem_u32(sm);
    const int tid = threadIdx.x;
    const int wid = tid >> 5, lane = tid & 31;
    const int grp = tid >> 8;            // barrier group 0/1
    const int tig256 = tid & 255;        // tid within group
    const int g8 = lane >> 2, tig = lane & 3;

    // one-time: weights (96KB) + biases -> smem (all 512 threads)
    {
        const uint4* src = (const uint4*)g_Wh;
        uint4* dst = (uint4*)(sm + WOFF);
        #pragma unroll
        for (int i = 0; i < 12; ++i) dst[tid + i * THR_A] = src[tid + i * THR_A];
        float* bsw = (float*)(sm + BIAS);
        #pragma unroll
        for (int i = 0; i < 2; ++i) {
            int idx = tid + i * THR_A;
            if (idx < 4 * NW) bsw[idx] = ((const float*)g_Bp)[idx];
        }
    }
    __syncthreads();                     // weights immutable hereafter
    const float* bs = (const float*)(sm + BIAS);

    // group-local warp layout: 8 warps = 4 m-tiles x 2 n-halves
    const int wg = wid & 7;
    const int lt = lane >> 3, lr = lane & 7;
    const int mrow = (wg & 3) * 16, half = wg >> 2;
    const int n0 = half * 96, chb = half * 32;
    const uint32_t AG = ABUF + (uint32_t)grp * 32768;   // group's buffer base
    const int arow = mrow + ((lt & 1) << 3) + lr;
    const uint32_t a_rowoff = (uint32_t)arow * 128;
    const uint32_t aswz = ((uint32_t)arow & 7) << 4;
    const int akadd = (lt >> 1) << 4;
    const int brow0 = n0 + ((lt >> 1) << 3) + lr;
    const uint32_t b_rowoff0 = (uint32_t)brow0 * 128;
    const uint32_t bswz = ((uint32_t)brow0 & 7) << 4;
    const int bkadd = (lt & 1) << 4;
    const int m1 = mrow + g8, m2 = m1 + 8;
    const int bar = grp + 1;

    for (int t = blockIdx.x * 2 + grp; t < NTILES; t += GRID_A * 2) {
        // stage input tile into buf0 (hi at +0, lo at +8192); overlaps prev L3
        {
            const float4* xin = (const float4*)(x + (size_t)t * MTILE * CH);
            #pragma unroll
            for (int i = 0; i < 4; ++i) {
                int fi = tig256 + i * 256;          // 1024 float4
                int pos = fi >> 4, c = (fi & 15) << 2;
                float4 v = xin[fi];
                uint32_t b = (uint32_t)pos * 128 + (((uint32_t)(2 * c)) ^ (((uint32_t)pos & 7) << 4));
                *(u64*)(sm + AG + b) = pack4hf(v.x, v.y, v.z, v.w);
                *(u64*)(sm + AG + 8192 + b) = pack4hf(
                    v.x - h2f(f2h(v.x)), v.y - h2f(f2h(v.y)),
                    v.z - h2f(f2h(v.z)), v.w - h2f(f2h(v.w)));
            }
        }
        GBAR(bar);

        #pragma unroll 1
        for (int l = 0; l < 4; ++l) {
            const uint32_t rbuf = AG + (uint32_t)(l & 1) * 16384;        // read buf
            const uint32_t wbuf = AG + (uint32_t)((l + 1) & 1) * 16384;  // write buf

            float acc[12][4];
            #pragma unroll
            for (int nt = 0; nt < 12; ++nt)
                #pragma unroll
                for (int r = 0; r < 4; ++r) acc[nt][r] = 0.f;

            const uint32_t Babs = sb + WOFF + (uint32_t)l * WLSZ + b_rowoff0;
            #pragma unroll
            for (int s = 0; s < 2; ++s) {
                const uint32_t Aabs = sb + rbuf + (uint32_t)s * 8192 + a_rowoff;
                #pragma unroll
                for (int ks = 0; ks < 4; ++ks) {
                    const uint32_t kb = ks * 32;
                    uint32_t a[4];
                    LDSM_X4(a, Aabs + ((kb + akadd) ^ aswz));
                    #pragma unroll
                    for (int np = 0; np < 6; ++np) {
                        uint32_t b[4];
                        LDSM_X4(b, Babs + (uint32_t)np * 2048 + ((kb + bkadd) ^ bswz));
                        mma16816(acc[2 * np],     a, b[0], b[1]);
                        mma16816(acc[2 * np + 1], a, b[2], b[3]);
                    }
                }
            }

            // register gate epilogue: acc[3j]=i, acc[3j+1]=g, acc[3j+2]=o
            float hreg[4][4];
            const float* bl = bs + l * NW + n0 + 2 * tig;
            #pragma unroll
            for (int j = 0; j < 4; ++j) {
                float2 bi = *(const float2*)(bl + j * 24);
                float2 bg = *(const float2*)(bl + j * 24 + 8);
                float2 bo = *(const float2*)(bl + j * 24 + 16);
                const float* ai = acc[3 * j];
                const float* ag = acc[3 * j + 1];
                const float* ao = acc[3 * j + 2];
                hreg[j][0] = hsig(ao[0] + bo.x) * tanh_fast(hsig(ai[0] + bi.x) * tanh_fast(ag[0] + bg.x));
                hreg[j][1] = hsig(ao[1] + bo.y) * tanh_fast(hsig(ai[1] + bi.y) * tanh_fast(ag[1] + bg.y));
                hreg[j][2] = hsig(ao[2] + bo.x) * tanh_fast(hsig(ai[2] + bi.x) * tanh_fast(ag[2] + bg.x));
                hreg[j][3] = hsig(ao[3] + bo.y) * tanh_fast(hsig(ai[3] + bi.y) * tanh_fast(ag[3] + bg.y));
            }

            if (l < 3) {
                // ping-pong: write into wbuf (untouched by this layer's reads)
                #pragma unroll
                for (int j = 0; j < 4; ++j) {
                    int c0 = chb + j * 8 + 2 * tig;
                    float r00 = hreg[j][0] - h2f(f2h(hreg[j][0]));
                    float r01 = hreg[j][1] - h2f(f2h(hreg[j][1]));
                    float r10 = hreg[j][2] - h2f(f2h(hreg[j][2]));
                    float r11 = hreg[j][3] - h2f(f2h(hreg[j][3]));
                    uint32_t b1o = (uint32_t)m1 * 128 + (((uint32_t)(2 * c0)) ^ (((uint32_t)m1 & 7) << 4));
                    uint32_t b2o = (uint32_t)m2 * 128 + (((uint32_t)(2 * c0)) ^ (((uint32_t)m2 & 7) << 4));
                    *(uint32_t*)(sm + wbuf + b1o) = pk2hf(hreg[j][0], hreg[j][1]);
                    *(uint32_t*)(sm + wbuf + 8192 + b1o) = pk2hf(r00, r01);
                    *(uint32_t*)(sm + wbuf + b2o) = pk2hf(hreg[j][2], hreg[j][3]);
                    *(uint32_t*)(sm + wbuf + 8192 + b2o) = pk2hf(r10, r11);
                }
                GBAR(bar);   // writes visible before next layer's reads
            } else {
                const size_t p0 = (size_t)t * MTILE;
                #pragma unroll
                for (int j = 0; j < 4; ++j) {
                    int c0 = chb + j * 8 + 2 * tig;
                    *(float2*)&g_h4[(p0 + m1) * CH + c0] = make_float2(hreg[j][0], hreg[j][1]);
                    *(float2*)&g_h4[(p0 + m2) * CH + c0] = make_float2(hreg[j][2], hreg[j][3]);
                }
            }
        }
    }
}

// ---------------------------------------------------------------------------
// Kernel B: split-K GEMM  partial[g] = flat[:, kb:kb+128] @ D1w[kb:kb+128, :]
// ---------------------------------------------------------------------------
__global__ void __launch_bounds__(256) k_dense_split(const float* __restrict__ D1w)
{
    extern __shared__ float smf[];
    float* As  = smf;             // [64][128]
    float* Bsm = smf + 64 * KC;   // [128][64]
    const int tid = threadIdx.x;
    const size_t kbase = (size_t)blockIdx.x * KC;

    for (int i = tid; i < 64 * (KC / 4); i += 256) {
        int b = i / (KC / 4), kq = i % (KC / 4);
        ((float4*)As)[i] = *(const float4*)(g_h4 + (size_t)b * FLATK + kbase + (size_t)kq * 4);
    }
    {
        const float4* d1 = (const float4*)(D1w + kbase * 64);
        for (int i = tid; i < KC * 16; i += 256) ((float4*)Bsm)[i] = d1[i];
    }
    __syncthreads();

    const int tx = tid & 15, ty = tid >> 4;
    const int b0 = ty * 4, n0 = tx * 4;
    u64 acc[4][2] = {};
    #pragma unroll 4
    for (int k = 0; k < KC; ++k) {
        ulonglong2 bw = *(const ulonglong2*)&Bsm[k * 64 + n0];
        #pragma unroll
        for (int j = 0; j < 4; ++j) {
            float a = As[(b0 + j) * KC + k];
            u64 pa = pk2(a, a);
            acc[j][0] = ffma2(pa, bw.x, acc[j][0]);
            acc[j][1] = ffma2(pa, bw.y, acc[j][1]);
        }
    }
    float* dst = g_part + (size_t)blockIdx.x * 4096;
    #pragma unroll
    for (int j = 0; j < 4; ++j) {
        float a0, a1, a2, a3;
        upk2(acc[j][0], a0, a1);
        upk2(acc[j][1], a2, a3);
        *(float4*)&dst[(b0 + j) * 64 + n0] = make_float4(a0, a1, a2, a3);
    }
}

// ---------------------------------------------------------------------------
// Kernel C1: stage-1 reduce: 2048 blocks, each sums 32 g-slices for (b,chunk).
// ---------------------------------------------------------------------------
__global__ void k_red1()
{
    __shared__ float sred[256];
    const int blk = blockIdx.x;            // 2048 = 64 b x 32 chunks
    const int b = blk >> 5, chunk = blk & 31;
    const int tid = threadIdx.x;
    const int n = tid & 63, sub = tid >> 6;
    const float* p = g_part + (size_t)(chunk * 32 + sub * 8) * 4096 + (size_t)b * 64 + n;
    float s = 0.f;
    #pragma unroll
    for (int t = 0; t < 8; ++t) s += p[(size_t)t * 4096];
    sred[tid] = s;
    __syncthreads();
    if (tid < 64)
        g_red[chunk * 4096 + b * 64 + n] =
            sred[tid] + sred[tid + 64] + sred[tid + 128] + sred[tid + 192];
}

// ---------------------------------------------------------------------------
// Kernel C2: final: sum 32 chunks + D1b + relu + D2 GEMV. 64 blocks x 64 thr.
// ---------------------------------------------------------------------------
__global__ void k_final(const float* __restrict__ D1b, const float* __restrict__ D2w,
                        const float* __restrict__ D2b, float* __restrict__ out)
{
    __shared__ float sA[2];
    const int b = blockIdx.x, n = threadIdx.x;   // 64 threads
    float v = 0.f;
    #pragma unroll
    for (int ch = 0; ch < RCH; ++ch) v += g_red[ch * 4096 + b * 64 + n];
    float y = fmaxf(v + D1b[n], 0.f) * D2w[n];
    #pragma unroll
    for (int off = 16; off > 0; off >>= 1)
        y += __shfl_down_sync(0xffffffffu, y, off);
    if ((n & 31) == 0) sA[n >> 5] = y;
    __syncthreads();
    if (n == 0) out[b] = sA[0] + sA[1] + D2b[0];
}

// ---------------------------------------------------------------------------
extern "C" void kernel_launch(void* const* d_in, const int* in_sizes, int n_in,
                              void* d_out, int out_size)
{
    const float* x   = (const float*)d_in[0];
    const float* W1x = (const float*)d_in[1];
    const float* b1  = (const float*)d_in[3];
    const float* W2x = (const float*)d_in[4];
    const float* b2  = (const float*)d_in[6];
    const float* W3x = (const float*)d_in[7];
    const float* b3  = (const float*)d_in[9];
    const float* W4x = (const float*)d_in[10];
    const float* b4  = (const float*)d_in[12];
    const float* D1w = (const float*)d_in[13];
    const float* D1b = (const float*)d_in[14];
    const float* D2w = (const float*)d_in[15];
    const float* D2b = (const float*)d_in[16];

    const int smemB = (64 * KC + KC * 64) * 4;   // 65536 B
    cudaFuncSetAttribute(k_lstm4, cudaFuncAttributeMaxDynamicSharedMemorySize, SMEM_A_TOT);
    cudaFuncSetAttribute(k_dense_split, cudaFuncAttributeMaxDynamicSharedMemorySize, smemB);

    // SAME padding over H=1 picks exactly one kernel row: r=4 (kh=10), r=2 (kh=5)
    k_prep<<<4, 256>>>(W1x + 4 * 64 * 256, W2x + 2 * 64 * 256,
                       W3x + 4 * 64 * 256, W4x + 2 * 64 * 256,
                       b1, b2, b3, b4);
    k_lstm4<<<GRID_A, THR_A, SMEM_A_TOT>>>(x);
    k_dense_split<<<GSPLIT, 256, smemB>>>(D1w);
    k_red1<<<2048, 256>>>();
    k_final<<<BATCH, 64>>>(D1b, D2w, D2b, (float*)d_out);
}